// round 5
// baseline (speedup 1.0000x reference)
#include <cuda_runtime.h>
#include <cuda_bf16.h>
#include <math.h>

#define V_SZ 2048
#define L_SZ 16
#define H_SZ 8
#define D_SZ 64
#define B_SZ 8192
#define NW_TOTAL 8192
#define N_NAMES 2048
#define TEMP_INV 0.125f

// -------- scratch --------
__device__ float g_cq[V_SZ * H_SZ * D_SZ];
__device__ float g_ck[V_SZ * H_SZ * D_SZ];
__device__ float g_cv[V_SZ * H_SZ * D_SZ];
__device__ float g_pq[L_SZ * H_SZ * D_SZ];
__device__ float g_pk[L_SZ * H_SZ * D_SZ];
__device__ float g_pv[L_SZ * H_SZ * D_SZ];
__device__ float g_qk[H_SZ * V_SZ * V_SZ];       // 134MB: char_qk[h][x][y]
__device__ float g_cp[H_SZ * V_SZ * L_SZ];       // cp[h][v][l]
__device__ float g_posqk[H_SZ * L_SZ * L_SZ];    // pos_qk[h][i][j]
__device__ float g_pooled[B_SZ * H_SZ * D_SZ];
__device__ float g_xflat[B_SZ * 512];
__device__ int   g_segoff[N_NAMES];

// -------- K0: pos embedding -> pq/pk/pv --------
__global__ void qkv_pos_kernel(const float* __restrict__ Wp, const float* __restrict__ bp) {
    int l = blockIdx.x;
    __shared__ float sp[64];
    int tid = threadIdx.x;
    if (tid < 64) {
        int f = tid & 31;
        double inv = pow(10000.0, -(double)f / 32.0);
        double ph = (double)l * inv;
        sp[tid] = (float)((tid < 32) ? cos(ph) : sin(ph));
    }
    __syncthreads();
    for (int c = tid; c < 1536; c += 256) {
        float a = 0.f;
        #pragma unroll 8
        for (int k = 0; k < 64; k++) a += sp[k] * Wp[k * 1536 + c];
        a += bp[c];
        int t = c >> 9, rem = c & 511;
        float* dst = (t == 0) ? g_pq : (t == 1) ? g_pk : g_pv;
        dst[l * 512 + rem] = a;
    }
}

// -------- K1: char_emb @ Wc + bc -> cq/ck/cv --------
__global__ __launch_bounds__(256) void qkv_char_kernel(
    const float* __restrict__ emb, const float* __restrict__ Wc, const float* __restrict__ bc) {
    int row0 = blockIdx.x * 8;
    __shared__ float se[8][64];
    int tid = threadIdx.x;
    for (int idx = tid; idx < 512; idx += 256)
        se[idx >> 6][idx & 63] = emb[(row0 + (idx >> 6)) * 64 + (idx & 63)];
    __syncthreads();
    float acc[6][8];
    #pragma unroll
    for (int c = 0; c < 6; c++)
        #pragma unroll
        for (int r = 0; r < 8; r++) acc[c][r] = 0.f;
    for (int k = 0; k < 64; k++) {
        float w[6];
        #pragma unroll
        for (int c = 0; c < 6; c++) w[c] = Wc[k * 1536 + tid + c * 256];
        #pragma unroll
        for (int r = 0; r < 8; r++) {
            float e = se[r][k];
            #pragma unroll
            for (int c = 0; c < 6; c++) acc[c][r] = fmaf(e, w[c], acc[c][r]);
        }
    }
    #pragma unroll
    for (int c = 0; c < 6; c++) {
        int col = tid + c * 256;
        float bias = bc[col];
        int t = col >> 9, rem = col & 511;
        float* dst = (t == 0) ? g_cq : (t == 1) ? g_ck : g_cv;
        #pragma unroll
        for (int r = 0; r < 8; r++) dst[(row0 + r) * 512 + rem] = acc[c][r] + bias;
    }
}

// -------- K2: char_qk GEMM --------
__global__ __launch_bounds__(256) void charqk_kernel() {
    __shared__ float sA[32][128];
    __shared__ float sB[32][128];
    int tid = threadIdx.x;
    int X0 = blockIdx.x * 128, Y0 = blockIdx.y * 128, h = blockIdx.z;
    int tx = tid & 15, ty = tid >> 4;
    int x0 = ty * 8, y0 = tx * 8;
    float acc[8][8];
    #pragma unroll
    for (int r = 0; r < 8; r++)
        #pragma unroll
        for (int c = 0; c < 8; c++) acc[r][c] = 0.f;

    int lx = tid & 127;
    int d0 = (tid >> 7) * 16;

    for (int kc = 0; kc < 2; kc++) {
        int gk = h * 64 + kc * 32 + d0;
        #pragma unroll
        for (int i = 0; i < 4; i++) {
            float4 a4 = *(const float4*)&g_cq[(X0 + lx) * 512 + gk + i * 4];
            float4 b4 = *(const float4*)&g_ck[(Y0 + lx) * 512 + gk + i * 4];
            int kk = d0 + i * 4;
            sA[kk + 0][lx] = a4.x; sA[kk + 1][lx] = a4.y; sA[kk + 2][lx] = a4.z; sA[kk + 3][lx] = a4.w;
            sB[kk + 0][lx] = b4.x; sB[kk + 1][lx] = b4.y; sB[kk + 2][lx] = b4.z; sB[kk + 3][lx] = b4.w;
        }
        __syncthreads();
        #pragma unroll
        for (int k = 0; k < 32; k++) {
            float4 aA = *(const float4*)&sA[k][x0];
            float4 aB = *(const float4*)&sA[k][x0 + 4];
            float4 bA = *(const float4*)&sB[k][y0];
            float4 bB = *(const float4*)&sB[k][y0 + 4];
            float av[8] = {aA.x, aA.y, aA.z, aA.w, aB.x, aB.y, aB.z, aB.w};
            float bv[8] = {bA.x, bA.y, bA.z, bA.w, bB.x, bB.y, bB.z, bB.w};
            #pragma unroll
            for (int r = 0; r < 8; r++)
                #pragma unroll
                for (int c = 0; c < 8; c++) acc[r][c] = fmaf(av[r], bv[c], acc[r][c]);
        }
        __syncthreads();
    }
    #pragma unroll
    for (int r = 0; r < 8; r++) {
        float* dst = &g_qk[h * (V_SZ * V_SZ) + (X0 + x0 + r) * V_SZ + Y0 + y0];
        *(float4*)dst       = make_float4(acc[r][0], acc[r][1], acc[r][2], acc[r][3]);
        *(float4*)(dst + 4) = make_float4(acc[r][4], acc[r][5], acc[r][6], acc[r][7]);
    }
}

// -------- K3: cp[h][v][j] = cq_v·pk_j + pq_j·ck_v --------
// grid (8, 8): block = (h, 256 v's). pk/pq staged transposed in smem -> broadcast reads.
__global__ __launch_bounds__(256) void cp_kernel() {
    __shared__ float sPK[64 * 16];   // [d][j]
    __shared__ float sPQ[64 * 16];
    int t = threadIdx.x;
    int h = blockIdx.x;
    int v = blockIdx.y * 256 + t;
    for (int idx = t; idx < 1024; idx += 256) {
        int j = idx >> 6, d = idx & 63;
        sPK[d * 16 + j] = g_pk[j * 512 + h * 64 + d];
        sPQ[d * 16 + j] = g_pq[j * 512 + h * 64 + d];
    }
    __syncthreads();
    float acc[16];
    #pragma unroll
    for (int j = 0; j < 16; j++) acc[j] = 0.f;
    const float* cqp = &g_cq[v * 512 + h * 64];
    const float* ckp = &g_ck[v * 512 + h * 64];
    #pragma unroll 4
    for (int d4 = 0; d4 < 64; d4 += 4) {
        float4 cq4 = *(const float4*)&cqp[d4];
        float4 ck4 = *(const float4*)&ckp[d4];
        float cqv[4] = {cq4.x, cq4.y, cq4.z, cq4.w};
        float ckv[4] = {ck4.x, ck4.y, ck4.z, ck4.w};
        #pragma unroll
        for (int dd = 0; dd < 4; dd++) {
            int d = d4 + dd;
            #pragma unroll
            for (int j4 = 0; j4 < 16; j4 += 4) {
                float4 pk4 = *(const float4*)&sPK[d * 16 + j4];
                float4 pq4 = *(const float4*)&sPQ[d * 16 + j4];
                acc[j4 + 0] = fmaf(cqv[dd], pk4.x, fmaf(ckv[dd], pq4.x, acc[j4 + 0]));
                acc[j4 + 1] = fmaf(cqv[dd], pk4.y, fmaf(ckv[dd], pq4.y, acc[j4 + 1]));
                acc[j4 + 2] = fmaf(cqv[dd], pk4.z, fmaf(ckv[dd], pq4.z, acc[j4 + 2]));
                acc[j4 + 3] = fmaf(cqv[dd], pk4.w, fmaf(ckv[dd], pq4.w, acc[j4 + 3]));
            }
        }
    }
    float* dst = &g_cp[(h * V_SZ + v) * 16];
    #pragma unroll
    for (int j4 = 0; j4 < 16; j4 += 4)
        *(float4*)&dst[j4] = make_float4(acc[j4], acc[j4 + 1], acc[j4 + 2], acc[j4 + 3]);
}

// -------- K4: pos_qk[h][i][j] --------
__global__ void posqk_kernel() {
    int t = threadIdx.x;
    int h = t >> 4, i = t & 15;
    for (int j = 0; j < 16; j++) {
        float a = 0.f;
        #pragma unroll
        for (int d = 0; d < 64; d += 4) {
            float4 q4 = *(const float4*)&g_pq[i * 512 + h * 64 + d];
            float4 k4 = *(const float4*)&g_pk[j * 512 + h * 64 + d];
            a += q4.x * k4.x + q4.y * k4.y + q4.z * k4.z + q4.w * k4.w;
        }
        g_posqk[(h << 8) + (i << 4) + j] = a;
    }
}

// -------- K_scan --------
__global__ void seg_scan_kernel(const int* __restrict__ nw) {
    __shared__ int s[N_NAMES];
    __shared__ int csum[32];
    int tid = threadIdx.x;
    for (int i = tid; i < N_NAMES; i += 256) s[i] = nw[i];
    __syncthreads();
    if (tid < 32) {
        int a = 0;
        for (int k = 0; k < 64; k++) a += s[tid * 64 + k];
        int x = a;
        #pragma unroll
        for (int o = 1; o < 32; o <<= 1) {
            int y = __shfl_up_sync(0xffffffff, x, o);
            if (tid >= o) x += y;
        }
        csum[tid] = x - a;
    }
    __syncthreads();
    if (tid < 32) {
        int off = csum[tid];
        for (int k = 0; k < 64; k++) {
            g_segoff[tid * 64 + k] = off;
            off += s[tid * 64 + k];
        }
    }
}

__device__ __forceinline__ float warp_sum(float x) {
    #pragma unroll
    for (int o = 16; o > 0; o >>= 1) x += __shfl_xor_sync(0xffffffff, x, o);
    return x;
}

// -------- K5: attention, all 8 heads per block (block per b, 256 thr) --------
__global__ __launch_bounds__(256) void attn_kernel(
    const int* __restrict__ code_g, const float* __restrict__ gamma, const float* __restrict__ beta) {
    __shared__ float sV[8 * 16 * 68];     // [h][p][68]
    __shared__ float S[8 * 16 * 17];      // [h][i][17] : exp values
    __shared__ float sinv[8 * 16];
    __shared__ int code[16];

    int t = threadIdx.x;
    int b = blockIdx.x;

    if (t < 16) code[t] = code_g[b * 16 + t];
    __syncthreads();

    // V gather: 2048 float4, 8 per thread
    #pragma unroll
    for (int e = t; e < 2048; e += 256) {
        int p = e >> 7, r = e & 127;         // r: (h, d4)
        int h = r >> 4, d4 = (r & 15) * 4;
        float4 cv4 = *(const float4*)&g_cv[code[p] * 512 + r * 4];
        float4 pv4 = *(const float4*)&g_pv[p * 512 + r * 4];
        float4 v;
        v.x = cv4.x + pv4.x; v.y = cv4.y + pv4.y; v.z = cv4.z + pv4.z; v.w = cv4.w + pv4.w;
        *(float4*)&sV[(h * 16 + p) * 68 + d4] = v;
    }

    // Score gather: 2048 entries, 8 per thread (independent -> high MLP)
    #pragma unroll
    for (int e = t; e < 2048; e += 256) {
        int h = e >> 8, r = e & 255;
        int i = r >> 4, j = r & 15;
        int cj = code[j];
        float val;
        if (cj == 0) {
            val = -1e9f;
        } else {
            int ci = code[i];
            val = (g_qk[(h << 22) + (ci << 11) + cj]
                 + g_cp[(((h << 11) + ci) << 4) + j]
                 + g_posqk[(h << 8) + r]) * TEMP_INV;
        }
        S[(h * 16 + i) * 17 + j] = val;
    }
    __syncthreads();

    // Softmax: 128 rows (h,i)
    if (t < 128) {
        float* row = &S[t * 17];
        float m = -1e30f;
        #pragma unroll
        for (int j = 0; j < 16; j++) m = fmaxf(m, row[j]);
        float sum = 0.f;
        #pragma unroll
        for (int j = 0; j < 16; j++) {
            float e = expf(row[j] - m);
            row[j] = e;
            sum += e;
        }
        sinv[t] = 1.f / sum;
    }
    __syncthreads();

    // AV + LN + pool: warp w = head w, lane owns 2 d's. All in registers.
    {
        int h = t >> 5, l = t & 31;
        int d0 = 2 * l;
        float g0 = gamma[d0], g1 = gamma[d0 + 1];
        float bt0 = beta[d0], bt1 = beta[d0 + 1];
        float p0 = 0.f, p1 = 0.f;
        int cnt = 0;
        #pragma unroll
        for (int i = 0; i < 16; i++) {
            if (code[i] == 0) continue;
            cnt++;
            float o0 = 0.f, o1 = 0.f;
            const float* srow = &S[(h * 16 + i) * 17];
            #pragma unroll
            for (int j = 0; j < 16; j++) {
                float pr = srow[j];
                float2 v2 = *(const float2*)&sV[(h * 16 + j) * 68 + d0];
                o0 = fmaf(pr, v2.x, o0);
                o1 = fmaf(pr, v2.y, o1);
            }
            float inv = sinv[h * 16 + i];
            o0 *= inv; o1 *= inv;
            float s = warp_sum(o0 + o1);
            float s2 = warp_sum(o0 * o0 + o1 * o1);
            float mu = s * (1.f / 64.f);
            float var = s2 * (1.f / 64.f) - mu * mu;
            float rstd = rsqrtf(var + 1e-5f);
            p0 += (o0 - mu) * rstd;
            p1 += (o1 - mu) * rstd;
        }
        float inv = 1.f / (float)cnt;
        g_pooled[b * 512 + h * 64 + d0]     = p0 * g0 * inv + bt0;
        g_pooled[b * 512 + h * 64 + d0 + 1] = p1 * g1 * inv + bt1;
    }
}

// -------- K6: MLP --------
__global__ __launch_bounds__(128) void mlp_kernel(
    const float* __restrict__ W1, const float* __restrict__ b1,
    const float* __restrict__ W2, const float* __restrict__ b2) {
    __shared__ float sW1[128], sB1[16], sW2[128], sB2[8];
    int tid = threadIdx.x;
    if (tid < 128) { sW1[tid] = W1[tid]; sW2[tid] = W2[tid]; }
    if (tid < 16) sB1[tid] = b1[tid];
    if (tid < 8)  sB2[tid] = b2[tid];
    __syncthreads();
    int b = blockIdx.x * 2 + (tid >> 6);
    int d = tid & 63;
    float hv[8];
    #pragma unroll
    for (int h = 0; h < 8; h++) hv[h] = g_pooled[b * 512 + h * 64 + d];
    float t[16];
    #pragma unroll
    for (int u = 0; u < 16; u++) {
        float a = sB1[u];
        #pragma unroll
        for (int h = 0; h < 8; h++) a = fmaf(hv[h], sW1[h * 16 + u], a);
        t[u] = fmaxf(a, 0.f);
    }
    #pragma unroll
    for (int o = 0; o < 8; o++) {
        float a = sB2[o];
        #pragma unroll
        for (int u = 0; u < 16; u++) a = fmaf(t[u], sW2[u * 8 + o], a);
        g_xflat[b * 512 + d * 8 + o] = a;
    }
}

// -------- K7: word gather + segment mean --------
__global__ void seg_kernel(const int* __restrict__ word_code,
                           const int* __restrict__ n_words,
                           float* __restrict__ out) {
    int n = blockIdx.x;
    int tid = threadIdx.x;
    int off = g_segoff[n];
    int cnt = n_words[n];
    float inv = 1.f / (float)cnt;
    for (int c = tid; c < 512; c += 256) {
        float a = 0.f;
        for (int w = 0; w < cnt; w++) {
            int wc = word_code[off + w];
            a += g_xflat[wc * 512 + c];
        }
        out[n * 512 + c] = a * inv;
    }
}

extern "C" void kernel_launch(void* const* d_in, const int* in_sizes, int n_in,
                              void* d_out, int out_size) {
    const float* char_emb = (const float*)d_in[0];
    const float* Wc       = (const float*)d_in[1];
    const float* bc       = (const float*)d_in[2];
    const float* Wp       = (const float*)d_in[3];
    const float* bp       = (const float*)d_in[4];
    const float* gamma    = (const float*)d_in[5];
    const float* beta     = (const float*)d_in[6];
    const float* W1       = (const float*)d_in[7];
    const float* b1       = (const float*)d_in[8];
    const float* W2       = (const float*)d_in[9];
    const float* b2       = (const float*)d_in[10];
    const int* char_code  = (const int*)d_in[11];
    const int* word_code  = (const int*)d_in[12];
    const int* n_words    = (const int*)d_in[13];
    float* out = (float*)d_out;

    qkv_pos_kernel<<<16, 256>>>(Wp, bp);
    qkv_char_kernel<<<256, 256>>>(char_emb, Wc, bc);
    posqk_kernel<<<1, 128>>>();
    charqk_kernel<<<dim3(16, 16, 8), 256>>>();      // 4th launch -> profiled
    cp_kernel<<<dim3(8, 8), 256>>>();
    seg_scan_kernel<<<1, 256>>>(n_words);
    attn_kernel<<<B_SZ, 256>>>(char_code, gamma, beta);
    mlp_kernel<<<B_SZ / 2, 128>>>(W1, b1, W2, b2);
    seg_kernel<<<N_NAMES, 256>>>(word_code, n_words, out);
}

// round 6
// speedup vs baseline: 1.3205x; 1.3205x over previous
#include <cuda_runtime.h>
#include <cuda_bf16.h>
#include <math.h>

#define V_SZ 2048
#define L_SZ 16
#define H_SZ 8
#define D_SZ 64
#define B_SZ 8192
#define NW_TOTAL 8192
#define N_NAMES 2048
#define TEMP_INV 0.125f

// -------- scratch --------
__device__ float g_cq[V_SZ * H_SZ * D_SZ];
__device__ float g_ck[V_SZ * H_SZ * D_SZ];
__device__ float g_cv[V_SZ * H_SZ * D_SZ];
__device__ float g_pq[L_SZ * H_SZ * D_SZ];
__device__ float g_pk[L_SZ * H_SZ * D_SZ];
__device__ float g_pv[L_SZ * H_SZ * D_SZ];
__device__ __nv_bfloat16 g_qkh[H_SZ * V_SZ * V_SZ];   // 67MB [h][x][y]
__device__ __nv_bfloat16 g_qkb[V_SZ * V_SZ * H_SZ];   // 67MB [x][y][h]
__device__ __nv_bfloat16 g_cpb[V_SZ * L_SZ * H_SZ];   // [v][j][h]
__device__ __nv_bfloat16 g_posb[L_SZ * L_SZ * H_SZ];  // [i][j][h]
__device__ float g_pooled[B_SZ * H_SZ * D_SZ];
__device__ float g_xflat[B_SZ * 512];
__device__ int   g_segoff[N_NAMES];

// -------- K0: pos embedding -> pq/pk/pv --------
__global__ void qkv_pos_kernel(const float* __restrict__ Wp, const float* __restrict__ bp) {
    int l = blockIdx.x;
    __shared__ float sp[64];
    int tid = threadIdx.x;
    if (tid < 64) {
        int f = tid & 31;
        double inv = pow(10000.0, -(double)f / 32.0);
        double ph = (double)l * inv;
        sp[tid] = (float)((tid < 32) ? cos(ph) : sin(ph));
    }
    __syncthreads();
    for (int c = tid; c < 1536; c += 256) {
        float a = 0.f;
        #pragma unroll 8
        for (int k = 0; k < 64; k++) a += sp[k] * Wp[k * 1536 + c];
        a += bp[c];
        int t = c >> 9, rem = c & 511;
        float* dst = (t == 0) ? g_pq : (t == 1) ? g_pk : g_pv;
        dst[l * 512 + rem] = a;
    }
}

// -------- K1: char_emb @ Wc + bc -> cq/ck/cv --------
__global__ __launch_bounds__(256) void qkv_char_kernel(
    const float* __restrict__ emb, const float* __restrict__ Wc, const float* __restrict__ bc) {
    int row0 = blockIdx.x * 8;
    __shared__ float se[8][64];
    int tid = threadIdx.x;
    for (int idx = tid; idx < 512; idx += 256)
        se[idx >> 6][idx & 63] = emb[(row0 + (idx >> 6)) * 64 + (idx & 63)];
    __syncthreads();
    float acc[6][8];
    #pragma unroll
    for (int c = 0; c < 6; c++)
        #pragma unroll
        for (int r = 0; r < 8; r++) acc[c][r] = 0.f;
    for (int k = 0; k < 64; k++) {
        float w[6];
        #pragma unroll
        for (int c = 0; c < 6; c++) w[c] = Wc[k * 1536 + tid + c * 256];
        #pragma unroll
        for (int r = 0; r < 8; r++) {
            float e = se[r][k];
            #pragma unroll
            for (int c = 0; c < 6; c++) acc[c][r] = fmaf(e, w[c], acc[c][r]);
        }
    }
    #pragma unroll
    for (int c = 0; c < 6; c++) {
        int col = tid + c * 256;
        float bias = bc[col];
        int t = col >> 9, rem = col & 511;
        float* dst = (t == 0) ? g_cq : (t == 1) ? g_ck : g_cv;
        #pragma unroll
        for (int r = 0; r < 8; r++) dst[(row0 + r) * 512 + rem] = acc[c][r] + bias;
    }
}

// -------- K2: char_qk GEMM -> bf16 [h][x][y] --------
__global__ __launch_bounds__(256) void charqk_kernel() {
    __shared__ float sA[32][128];
    __shared__ float sB[32][128];
    int tid = threadIdx.x;
    int X0 = blockIdx.x * 128, Y0 = blockIdx.y * 128, h = blockIdx.z;
    int tx = tid & 15, ty = tid >> 4;
    int x0 = ty * 8, y0 = tx * 8;
    float acc[8][8];
    #pragma unroll
    for (int r = 0; r < 8; r++)
        #pragma unroll
        for (int c = 0; c < 8; c++) acc[r][c] = 0.f;

    int lx = tid & 127;
    int d0 = (tid >> 7) * 16;

    for (int kc = 0; kc < 2; kc++) {
        int gk = h * 64 + kc * 32 + d0;
        #pragma unroll
        for (int i = 0; i < 4; i++) {
            float4 a4 = *(const float4*)&g_cq[(X0 + lx) * 512 + gk + i * 4];
            float4 b4 = *(const float4*)&g_ck[(Y0 + lx) * 512 + gk + i * 4];
            int kk = d0 + i * 4;
            sA[kk + 0][lx] = a4.x; sA[kk + 1][lx] = a4.y; sA[kk + 2][lx] = a4.z; sA[kk + 3][lx] = a4.w;
            sB[kk + 0][lx] = b4.x; sB[kk + 1][lx] = b4.y; sB[kk + 2][lx] = b4.z; sB[kk + 3][lx] = b4.w;
        }
        __syncthreads();
        #pragma unroll
        for (int k = 0; k < 32; k++) {
            float4 aA = *(const float4*)&sA[k][x0];
            float4 aB = *(const float4*)&sA[k][x0 + 4];
            float4 bA = *(const float4*)&sB[k][y0];
            float4 bB = *(const float4*)&sB[k][y0 + 4];
            float av[8] = {aA.x, aA.y, aA.z, aA.w, aB.x, aB.y, aB.z, aB.w};
            float bv[8] = {bA.x, bA.y, bA.z, bA.w, bB.x, bB.y, bB.z, bB.w};
            #pragma unroll
            for (int r = 0; r < 8; r++)
                #pragma unroll
                for (int c = 0; c < 8; c++) acc[r][c] = fmaf(av[r], bv[c], acc[r][c]);
        }
        __syncthreads();
    }
    #pragma unroll
    for (int r = 0; r < 8; r++) {
        __nv_bfloat16 tmp[8];
        #pragma unroll
        for (int c = 0; c < 8; c++) tmp[c] = __float2bfloat16(acc[r][c]);
        *(uint4*)&g_qkh[h * (V_SZ * V_SZ) + (X0 + x0 + r) * V_SZ + Y0 + y0] = *(uint4*)tmp;
    }
}

// -------- K3: transpose [h][x][y] -> [x][y][h] --------
__global__ __launch_bounds__(256) void qk_transpose_kernel() {
    int t = threadIdx.x;
    int bx = blockIdx.x;                 // 16384
    int x = bx >> 3;
    int y = ((bx & 7) << 8) + t;
    __nv_bfloat16 tmp[8];
    #pragma unroll
    for (int h = 0; h < 8; h++)
        tmp[h] = g_qkh[h * (V_SZ * V_SZ) + x * V_SZ + y];
    *(uint4*)&g_qkb[((size_t)(x * V_SZ + y)) * 8] = *(uint4*)tmp;
}

// -------- K4: cp[v][j][h] bf16 + posqk[i][j][h] bf16 --------
// grid 257 x block 128. blocks 0..255: 8 v's each. block 256: posqk.
__global__ __launch_bounds__(128) void cppos_kernel() {
    int t = threadIdx.x;
    if (blockIdx.x == 256) {
        for (int e = t; e < 256; e += 128) {
            int i = e >> 4, j = e & 15;
            __nv_bfloat16 tmp[8];
            #pragma unroll
            for (int h = 0; h < 8; h++) {
                float a = 0.f;
                #pragma unroll
                for (int d = 0; d < 64; d += 4) {
                    float4 q4 = *(const float4*)&g_pq[i * 512 + h * 64 + d];
                    float4 k4 = *(const float4*)&g_pk[j * 512 + h * 64 + d];
                    a += q4.x * k4.x + q4.y * k4.y + q4.z * k4.z + q4.w * k4.w;
                }
                tmp[h] = __float2bfloat16(a);
            }
            *(uint4*)&g_posb[e * 8] = *(uint4*)tmp;
        }
        return;
    }
    int v0 = blockIdx.x * 8;
    __shared__ float scq[8 * 512], sck[8 * 512];
    for (int idx = t; idx < 1024; idx += 128) {
        *(float4*)&scq[idx * 4] = *(const float4*)&g_cq[v0 * 512 + idx * 4];
        *(float4*)&sck[idx * 4] = *(const float4*)&g_ck[v0 * 512 + idx * 4];
    }
    __syncthreads();
    int v = t >> 4, j = t & 15;
    __nv_bfloat16 tmp[8];
    #pragma unroll
    for (int h = 0; h < 8; h++) {
        float d1 = 0.f, d2 = 0.f;
        #pragma unroll
        for (int d = 0; d < 64; d += 4) {
            float4 pk4 = *(const float4*)&g_pk[j * 512 + h * 64 + d];
            float4 pq4 = *(const float4*)&g_pq[j * 512 + h * 64 + d];
            float4 cq4 = *(const float4*)&scq[v * 512 + h * 64 + d];
            float4 ck4 = *(const float4*)&sck[v * 512 + h * 64 + d];
            d1 += cq4.x * pk4.x + cq4.y * pk4.y + cq4.z * pk4.z + cq4.w * pk4.w;
            d2 += pq4.x * ck4.x + pq4.y * ck4.y + pq4.z * ck4.z + pq4.w * ck4.w;
        }
        tmp[h] = __float2bfloat16(d1 + d2);
    }
    *(uint4*)&g_cpb[((v0 + v) * 16 + j) * 8] = *(uint4*)tmp;
}

// -------- K_scan --------
__global__ void seg_scan_kernel(const int* __restrict__ nw) {
    __shared__ int s[N_NAMES];
    __shared__ int csum[32];
    int tid = threadIdx.x;
    for (int i = tid; i < N_NAMES; i += 256) s[i] = nw[i];
    __syncthreads();
    if (tid < 32) {
        int a = 0;
        for (int k = 0; k < 64; k++) a += s[tid * 64 + k];
        int x = a;
        #pragma unroll
        for (int o = 1; o < 32; o <<= 1) {
            int y = __shfl_up_sync(0xffffffff, x, o);
            if (tid >= o) x += y;
        }
        csum[tid] = x - a;
    }
    __syncthreads();
    if (tid < 32) {
        int off = csum[tid];
        for (int k = 0; k < 64; k++) {
            g_segoff[tid * 64 + k] = off;
            off += s[tid * 64 + k];
        }
    }
}

__device__ __forceinline__ float warp_sum(float x) {
    #pragma unroll
    for (int o = 16; o > 0; o >>= 1) x += __shfl_xor_sync(0xffffffff, x, o);
    return x;
}

// -------- K5: attention, all 8 heads per block (block per b, 256 thr) --------
__global__ __launch_bounds__(256) void attn_kernel(
    const int* __restrict__ code_g, const float* __restrict__ gamma, const float* __restrict__ beta) {
    __shared__ float sV[8 * 16 * 68];     // [h][p][68]
    __shared__ float S[8 * 16 * 17];      // [h][i][17]
    __shared__ float sinv[128];
    __shared__ int code[16];

    int t = threadIdx.x;
    int b = blockIdx.x;

    if (t < 16) code[t] = code_g[b * 16 + t];
    __syncthreads();

    // V gather: 2048 float4, 8 per thread
    #pragma unroll
    for (int e = t; e < 2048; e += 256) {
        int p = e >> 7, r = e & 127;         // r = h*16 + d4/4
        int h = r >> 4, d4 = (r & 15) * 4;
        float4 cv4 = *(const float4*)&g_cv[code[p] * 512 + r * 4];
        float4 pv4 = *(const float4*)&g_pv[p * 512 + r * 4];
        float4 v;
        v.x = cv4.x + pv4.x; v.y = cv4.y + pv4.y; v.z = cv4.z + pv4.z; v.w = cv4.w + pv4.w;
        *(float4*)&sV[(h * 16 + p) * 68 + d4] = v;
    }

    // Score gather: one (i,j) per thread, 8 heads per 16B sector
    {
        int i = t >> 4, j = t & 15;
        int cj = code[j];
        if (cj == 0) {
            #pragma unroll
            for (int h = 0; h < 8; h++) S[(h * 16 + i) * 17 + j] = -1e9f;
        } else {
            int ci = code[i];
            uint4 qk8u = *(const uint4*)&g_qkb[((size_t)((ci << 11) + cj)) * 8];
            uint4 cp8u = *(const uint4*)&g_cpb[((ci << 4) + j) * 8];
            uint4 ps8u = *(const uint4*)&g_posb[((i << 4) + j) * 8];
            const __nv_bfloat16* qk8 = (const __nv_bfloat16*)&qk8u;
            const __nv_bfloat16* cp8 = (const __nv_bfloat16*)&cp8u;
            const __nv_bfloat16* ps8 = (const __nv_bfloat16*)&ps8u;
            #pragma unroll
            for (int h = 0; h < 8; h++) {
                float s = __bfloat162float(qk8[h]) + __bfloat162float(cp8[h]) + __bfloat162float(ps8[h]);
                S[(h * 16 + i) * 17 + j] = s * TEMP_INV;
            }
        }
    }
    __syncthreads();

    // Softmax: 128 rows (h,i)
    if (t < 128) {
        float* row = &S[t * 17];
        float m = -1e30f;
        #pragma unroll
        for (int j = 0; j < 16; j++) m = fmaxf(m, row[j]);
        float sum = 0.f;
        #pragma unroll
        for (int j = 0; j < 16; j++) {
            float e = expf(row[j] - m);
            row[j] = e;
            sum += e;
        }
        sinv[t] = 1.f / sum;
    }
    __syncthreads();

    // AV + LN + pool: warp = head, lane owns 2 d's.
    {
        int h = t >> 5, l = t & 31;
        int d0 = 2 * l;
        float g0 = gamma[d0], g1 = gamma[d0 + 1];
        float bt0 = beta[d0], bt1 = beta[d0 + 1];
        float p0 = 0.f, p1 = 0.f;
        int cnt = 0;
        #pragma unroll
        for (int i = 0; i < 16; i++) {
            if (code[i] == 0) continue;
            cnt++;
            float o0 = 0.f, o1 = 0.f;
            const float* srow = &S[(h * 16 + i) * 17];
            #pragma unroll
            for (int j = 0; j < 16; j++) {
                float pr = srow[j];
                float2 v2 = *(const float2*)&sV[(h * 16 + j) * 68 + d0];
                o0 = fmaf(pr, v2.x, o0);
                o1 = fmaf(pr, v2.y, o1);
            }
            float inv = sinv[h * 16 + i];
            o0 *= inv; o1 *= inv;
            float s = warp_sum(o0 + o1);
            float s2 = warp_sum(o0 * o0 + o1 * o1);
            float mu = s * (1.f / 64.f);
            float var = s2 * (1.f / 64.f) - mu * mu;
            float rstd = rsqrtf(var + 1e-5f);
            p0 += (o0 - mu) * rstd;
            p1 += (o1 - mu) * rstd;
        }
        float inv = 1.f / (float)cnt;
        g_pooled[b * 512 + h * 64 + d0]     = p0 * g0 * inv + bt0;
        g_pooled[b * 512 + h * 64 + d0 + 1] = p1 * g1 * inv + bt1;
    }
}

// -------- K6: MLP --------
__global__ __launch_bounds__(128) void mlp_kernel(
    const float* __restrict__ W1, const float* __restrict__ b1,
    const float* __restrict__ W2, const float* __restrict__ b2) {
    __shared__ float sW1[128], sB1[16], sW2[128], sB2[8];
    int tid = threadIdx.x;
    if (tid < 128) { sW1[tid] = W1[tid]; sW2[tid] = W2[tid]; }
    if (tid < 16) sB1[tid] = b1[tid];
    if (tid < 8)  sB2[tid] = b2[tid];
    __syncthreads();
    int b = blockIdx.x * 2 + (tid >> 6);
    int d = tid & 63;
    float hv[8];
    #pragma unroll
    for (int h = 0; h < 8; h++) hv[h] = g_pooled[b * 512 + h * 64 + d];
    float t[16];
    #pragma unroll
    for (int u = 0; u < 16; u++) {
        float a = sB1[u];
        #pragma unroll
        for (int h = 0; h < 8; h++) a = fmaf(hv[h], sW1[h * 16 + u], a);
        t[u] = fmaxf(a, 0.f);
    }
    #pragma unroll
    for (int o = 0; o < 8; o++) {
        float a = sB2[o];
        #pragma unroll
        for (int u = 0; u < 16; u++) a = fmaf(t[u], sW2[u * 8 + o], a);
        g_xflat[b * 512 + d * 8 + o] = a;
    }
}

// -------- K7: word gather + segment mean --------
__global__ void seg_kernel(const int* __restrict__ word_code,
                           const int* __restrict__ n_words,
                           float* __restrict__ out) {
    int n = blockIdx.x;
    int tid = threadIdx.x;
    int off = g_segoff[n];
    int cnt = n_words[n];
    float inv = 1.f / (float)cnt;
    for (int c = tid; c < 512; c += 256) {
        float a = 0.f;
        for (int w = 0; w < cnt; w++) {
            int wc = word_code[off + w];
            a += g_xflat[wc * 512 + c];
        }
        out[n * 512 + c] = a * inv;
    }
}

extern "C" void kernel_launch(void* const* d_in, const int* in_sizes, int n_in,
                              void* d_out, int out_size) {
    const float* char_emb = (const float*)d_in[0];
    const float* Wc       = (const float*)d_in[1];
    const float* bc       = (const float*)d_in[2];
    const float* Wp       = (const float*)d_in[3];
    const float* bp       = (const float*)d_in[4];
    const float* gamma    = (const float*)d_in[5];
    const float* beta     = (const float*)d_in[6];
    const float* W1       = (const float*)d_in[7];
    const float* b1       = (const float*)d_in[8];
    const float* W2       = (const float*)d_in[9];
    const float* b2       = (const float*)d_in[10];
    const int* char_code  = (const int*)d_in[11];
    const int* word_code  = (const int*)d_in[12];
    const int* n_words    = (const int*)d_in[13];
    float* out = (float*)d_out;

    qkv_pos_kernel<<<16, 256>>>(Wp, bp);                 // 1
    qkv_char_kernel<<<256, 256>>>(char_emb, Wc, bc);     // 2
    charqk_kernel<<<dim3(16, 16, 8), 256>>>();           // 3
    qk_transpose_kernel<<<16384, 256>>>();               // 4
    cppos_kernel<<<257, 128>>>();                        // 5
    attn_kernel<<<B_SZ, 256>>>(char_code, gamma, beta);  // 6 <- profiled
    seg_scan_kernel<<<1, 256>>>(n_words);                // 7
    mlp_kernel<<<B_SZ / 2, 128>>>(W1, b1, W2, b2);       // 8
    seg_kernel<<<N_NAMES, 256>>>(word_code, n_words, out); // 9
}

// round 8
// speedup vs baseline: 1.5992x; 1.2110x over previous
#include <cuda_runtime.h>
#include <cuda_bf16.h>
#include <math.h>
#include <cstdint>

#define V_SZ 2048
#define L_SZ 16
#define H_SZ 8
#define D_SZ 64
#define B_SZ 8192
#define NW_TOTAL 8192
#define N_NAMES 2048
#define TEMP_INV 0.125f

// -------- scratch --------
__device__ float g_cq[V_SZ * H_SZ * D_SZ];
__device__ float g_ck[V_SZ * H_SZ * D_SZ];
__device__ float g_cv[V_SZ * H_SZ * D_SZ];
__device__ __nv_bfloat16 g_cqb[V_SZ * 512];
__device__ __nv_bfloat16 g_ckb[V_SZ * 512];
__device__ float g_pq[L_SZ * H_SZ * D_SZ];
__device__ float g_pk[L_SZ * H_SZ * D_SZ];
__device__ float g_pv[L_SZ * H_SZ * D_SZ];
__device__ __nv_bfloat16 g_qkh[H_SZ * V_SZ * V_SZ];   // 67MB [h][x][y]
__device__ __nv_bfloat16 g_qkb[V_SZ * V_SZ * H_SZ];   // 67MB [x][y][h]
__device__ __nv_bfloat16 g_cpb[V_SZ * L_SZ * H_SZ];   // [v][j][h]
__device__ __nv_bfloat16 g_posb[L_SZ * L_SZ * H_SZ];  // [i][j][h]
__device__ float g_pooled[B_SZ * H_SZ * D_SZ];
__device__ float g_xflat[B_SZ * 512];
__device__ int   g_segoff[N_NAMES];

// -------- K0: pos embedding -> pq/pk/pv --------
__global__ void qkv_pos_kernel(const float* __restrict__ Wp, const float* __restrict__ bp) {
    int l = blockIdx.x;
    __shared__ float sp[64];
    int tid = threadIdx.x;
    if (tid < 64) {
        int f = tid & 31;
        double inv = pow(10000.0, -(double)f / 32.0);
        double ph = (double)l * inv;
        sp[tid] = (float)((tid < 32) ? cos(ph) : sin(ph));
    }
    __syncthreads();
    for (int c = tid; c < 1536; c += 256) {
        float a = 0.f;
        #pragma unroll 8
        for (int k = 0; k < 64; k++) a += sp[k] * Wp[k * 1536 + c];
        a += bp[c];
        int t = c >> 9, rem = c & 511;
        float* dst = (t == 0) ? g_pq : (t == 1) ? g_pk : g_pv;
        dst[l * 512 + rem] = a;
    }
}

// -------- K1: char_emb @ Wc + bc -> cq/ck/cv (+bf16 copies of cq/ck) --------
__global__ __launch_bounds__(256) void qkv_char_kernel(
    const float* __restrict__ emb, const float* __restrict__ Wc, const float* __restrict__ bc) {
    int row0 = blockIdx.x * 8;
    __shared__ float se[8][64];
    int tid = threadIdx.x;
    for (int idx = tid; idx < 512; idx += 256)
        se[idx >> 6][idx & 63] = emb[(row0 + (idx >> 6)) * 64 + (idx & 63)];
    __syncthreads();
    float acc[6][8];
    #pragma unroll
    for (int c = 0; c < 6; c++)
        #pragma unroll
        for (int r = 0; r < 8; r++) acc[c][r] = 0.f;
    for (int k = 0; k < 64; k++) {
        float w[6];
        #pragma unroll
        for (int c = 0; c < 6; c++) w[c] = Wc[k * 1536 + tid + c * 256];
        #pragma unroll
        for (int r = 0; r < 8; r++) {
            float e = se[r][k];
            #pragma unroll
            for (int c = 0; c < 6; c++) acc[c][r] = fmaf(e, w[c], acc[c][r]);
        }
    }
    #pragma unroll
    for (int c = 0; c < 6; c++) {
        int col = tid + c * 256;
        float bias = bc[col];
        int t = col >> 9, rem = col & 511;
        float* dst = (t == 0) ? g_cq : (t == 1) ? g_ck : g_cv;
        __nv_bfloat16* bdst = (t == 0) ? g_cqb : (t == 1) ? g_ckb : (__nv_bfloat16*)0;
        #pragma unroll
        for (int r = 0; r < 8; r++) {
            float val = acc[c][r] + bias;
            int idx = (row0 + r) * 512 + rem;
            dst[idx] = val;
            if (bdst) bdst[idx] = __float2bfloat16(val);
        }
    }
}

// -------- K2: char_qk GEMM via mma.sync bf16 -> bf16 [h][x][y] --------
__global__ __launch_bounds__(256) void charqk_mma_kernel() {
    __shared__ __align__(16) char smem_raw[36864];
    __nv_bfloat16* sA = (__nv_bfloat16*)smem_raw;            // [128][72]
    __nv_bfloat16* sB = sA + 128 * 72;                        // [128][72]

    int t = threadIdx.x;
    int lane = t & 31;
    int w = t >> 5;
    int X0 = blockIdx.x * 128, Y0 = blockIdx.y * 128, h = blockIdx.z;

    // load A (cq) and B (ck) tiles: 128 rows x 64 bf16 each
    {
        int row = t >> 1, half = t & 1;
        const uint4* srcA = (const uint4*)&g_cqb[(size_t)(X0 + row) * 512 + h * 64 + half * 32];
        const uint4* srcB = (const uint4*)&g_ckb[(size_t)(Y0 + row) * 512 + h * 64 + half * 32];
        uint4* dstA = (uint4*)&sA[row * 72 + half * 32];
        uint4* dstB = (uint4*)&sB[row * 72 + half * 32];
        #pragma unroll
        for (int k = 0; k < 4; k++) { dstA[k] = srcA[k]; dstB[k] = srcB[k]; }
    }
    __syncthreads();

    int wx = w >> 2, wy = w & 3;       // warp tile: rows wx*64, cols wy*32
    float c[4][4][4];
    #pragma unroll
    for (int mi = 0; mi < 4; mi++)
        #pragma unroll
        for (int ni = 0; ni < 4; ni++)
            #pragma unroll
            for (int e = 0; e < 4; e++) c[mi][ni][e] = 0.f;

    int arow = wx * 64 + (lane & 15);
    int acol_off = ((lane >> 4) & 1) * 8;
    int brow_base = wy * 32 + (lane & 7);
    int bcol_off = ((lane >> 3) & 1) * 8;

    #pragma unroll
    for (int k0 = 0; k0 < 64; k0 += 16) {
        unsigned int bfr[4][2];
        #pragma unroll
        for (int ni = 0; ni < 4; ni++) {
            unsigned int baddr = (unsigned int)__cvta_generic_to_shared(
                &sB[(brow_base + ni * 8) * 72 + k0 + bcol_off]);
            asm volatile("ldmatrix.sync.aligned.m8n8.x2.shared.b16 {%0,%1}, [%2];"
                         : "=r"(bfr[ni][0]), "=r"(bfr[ni][1]) : "r"(baddr));
        }
        #pragma unroll
        for (int mi = 0; mi < 4; mi++) {
            unsigned int afr[4];
            unsigned int aaddr = (unsigned int)__cvta_generic_to_shared(
                &sA[(arow + mi * 16) * 72 + k0 + acol_off]);
            asm volatile("ldmatrix.sync.aligned.m8n8.x4.shared.b16 {%0,%1,%2,%3}, [%4];"
                         : "=r"(afr[0]), "=r"(afr[1]), "=r"(afr[2]), "=r"(afr[3]) : "r"(aaddr));
            #pragma unroll
            for (int ni = 0; ni < 4; ni++) {
                asm volatile(
                    "mma.sync.aligned.m16n8k16.row.col.f32.bf16.bf16.f32 "
                    "{%0,%1,%2,%3}, {%4,%5,%6,%7}, {%8,%9}, {%0,%1,%2,%3};"
                    : "+f"(c[mi][ni][0]), "+f"(c[mi][ni][1]), "+f"(c[mi][ni][2]), "+f"(c[mi][ni][3])
                    : "r"(afr[0]), "r"(afr[1]), "r"(afr[2]), "r"(afr[3]),
                      "r"(bfr[ni][0]), "r"(bfr[ni][1]));
            }
        }
    }
    __syncthreads();   // everyone done reading sA/sB

    // stage bf16 output in smem [128][136] then write coalesced
    __nv_bfloat16* sOut = (__nv_bfloat16*)smem_raw;
    {
        int r0 = wx * 64 + (lane >> 2);
        int c0 = wy * 32 + (lane & 3) * 2;
        #pragma unroll
        for (int mi = 0; mi < 4; mi++)
            #pragma unroll
            for (int ni = 0; ni < 4; ni++) {
                int rr = r0 + mi * 16, cc = c0 + ni * 8;
                *(__nv_bfloat162*)&sOut[rr * 136 + cc] =
                    __float22bfloat162_rn(make_float2(c[mi][ni][0], c[mi][ni][1]));
                *(__nv_bfloat162*)&sOut[(rr + 8) * 136 + cc] =
                    __float22bfloat162_rn(make_float2(c[mi][ni][2], c[mi][ni][3]));
            }
    }
    __syncthreads();
    for (int idx = t; idx < 2048; idx += 256) {
        int row = idx >> 4, c16 = (idx & 15) * 8;
        uint4 v = *(uint4*)&sOut[row * 136 + c16];
        *(uint4*)&g_qkh[(size_t)h * V_SZ * V_SZ + (size_t)(X0 + row) * V_SZ + Y0 + c16] = v;
    }
}

// -------- K3: transpose [h][x][y] -> [x][y][h] --------
__global__ __launch_bounds__(256) void qk_transpose_kernel() {
    int t = threadIdx.x;
    int bx = blockIdx.x;
    int x = bx >> 3;
    int y = ((bx & 7) << 8) + t;
    __nv_bfloat16 tmp[8];
    #pragma unroll
    for (int h = 0; h < 8; h++)
        tmp[h] = g_qkh[h * (V_SZ * V_SZ) + x * V_SZ + y];
    *(uint4*)&g_qkb[((size_t)(x * V_SZ + y)) * 8] = *(uint4*)tmp;
}

// -------- K4: cp[v][j][h] bf16 + posqk[i][j][h] bf16 --------
__global__ __launch_bounds__(128) void cppos_kernel() {
    int t = threadIdx.x;
    if (blockIdx.x == 256) {
        for (int e = t; e < 256; e += 128) {
            int i = e >> 4, j = e & 15;
            __nv_bfloat16 tmp[8];
            #pragma unroll
            for (int h = 0; h < 8; h++) {
                float a = 0.f;
                #pragma unroll
                for (int d = 0; d < 64; d += 4) {
                    float4 q4 = *(const float4*)&g_pq[i * 512 + h * 64 + d];
                    float4 k4 = *(const float4*)&g_pk[j * 512 + h * 64 + d];
                    a += q4.x * k4.x + q4.y * k4.y + q4.z * k4.z + q4.w * k4.w;
                }
                tmp[h] = __float2bfloat16(a);
            }
            *(uint4*)&g_posb[e * 8] = *(uint4*)tmp;
        }
        return;
    }
    int v0 = blockIdx.x * 8;
    __shared__ float scq[8 * 512], sck[8 * 512];
    for (int idx = t; idx < 1024; idx += 128) {
        *(float4*)&scq[idx * 4] = *(const float4*)&g_cq[v0 * 512 + idx * 4];
        *(float4*)&sck[idx * 4] = *(const float4*)&g_ck[v0 * 512 + idx * 4];
    }
    __syncthreads();
    int v = t >> 4, j = t & 15;
    __nv_bfloat16 tmp[8];
    #pragma unroll
    for (int h = 0; h < 8; h++) {
        float d1 = 0.f, d2 = 0.f;
        #pragma unroll
        for (int d = 0; d < 64; d += 4) {
            float4 pk4 = *(const float4*)&g_pk[j * 512 + h * 64 + d];
            float4 pq4 = *(const float4*)&g_pq[j * 512 + h * 64 + d];
            float4 cq4 = *(const float4*)&scq[v * 512 + h * 64 + d];
            float4 ck4 = *(const float4*)&sck[v * 512 + h * 64 + d];
            d1 += cq4.x * pk4.x + cq4.y * pk4.y + cq4.z * pk4.z + cq4.w * pk4.w;
            d2 += pq4.x * ck4.x + pq4.y * ck4.y + pq4.z * ck4.z + pq4.w * ck4.w;
        }
        tmp[h] = __float2bfloat16(d1 + d2);
    }
    *(uint4*)&g_cpb[((v0 + v) * 16 + j) * 8] = *(uint4*)tmp;
}

// -------- K_scan --------
__global__ void seg_scan_kernel(const int* __restrict__ nw) {
    __shared__ int s[N_NAMES];
    __shared__ int csum[32];
    int tid = threadIdx.x;
    for (int i = tid; i < N_NAMES; i += 256) s[i] = nw[i];
    __syncthreads();
    if (tid < 32) {
        int a = 0;
        for (int k = 0; k < 64; k++) a += s[tid * 64 + k];
        int x = a;
        #pragma unroll
        for (int o = 1; o < 32; o <<= 1) {
            int y = __shfl_up_sync(0xffffffff, x, o);
            if (tid >= o) x += y;
        }
        csum[tid] = x - a;
    }
    __syncthreads();
    if (tid < 32) {
        int off = csum[tid];
        for (int k = 0; k < 64; k++) {
            g_segoff[tid * 64 + k] = off;
            off += s[tid * 64 + k];
        }
    }
}

// -------- K5: attention, all 8 heads per block (block per b, 256 thr) --------
__global__ __launch_bounds__(256) void attn_kernel(
    const int* __restrict__ code_g, const float* __restrict__ gamma, const float* __restrict__ beta) {
    __shared__ float sV[8 * 16 * 68];     // [h][p][68]
    __shared__ float S[8 * 16 * 17];      // [(h,i)][17] exp values
    __shared__ float sO[8 * 16 * 68];     // normalized rows
    __shared__ float sinv[128];
    __shared__ int code[16];

    int t = threadIdx.x;
    int b = blockIdx.x;

    if (t < 16) code[t] = code_g[b * 16 + t];
    __syncthreads();

    // V gather
    #pragma unroll
    for (int e = t; e < 2048; e += 256) {
        int p = e >> 7, r = e & 127;
        int h = r >> 4, d4 = (r & 15) * 4;
        float4 cv4 = *(const float4*)&g_cv[code[p] * 512 + r * 4];
        float4 pv4 = *(const float4*)&g_pv[p * 512 + r * 4];
        float4 v;
        v.x = cv4.x + pv4.x; v.y = cv4.y + pv4.y; v.z = cv4.z + pv4.z; v.w = cv4.w + pv4.w;
        *(float4*)&sV[(h * 16 + p) * 68 + d4] = v;
    }

    // Score gather: one (i,j) per thread, 8 heads per 16B sector
    {
        int i = t >> 4, j = t & 15;
        int cj = code[j];
        if (cj == 0) {
            #pragma unroll
            for (int h = 0; h < 8; h++) S[(h * 16 + i) * 17 + j] = -1e9f;
        } else {
            int ci = code[i];
            uint4 qk8u = *(const uint4*)&g_qkb[((size_t)((ci << 11) + cj)) * 8];
            uint4 cp8u = *(const uint4*)&g_cpb[((ci << 4) + j) * 8];
            uint4 ps8u = *(const uint4*)&g_posb[((i << 4) + j) * 8];
            const __nv_bfloat16* qk8 = (const __nv_bfloat16*)&qk8u;
            const __nv_bfloat16* cp8 = (const __nv_bfloat16*)&cp8u;
            const __nv_bfloat16* ps8 = (const __nv_bfloat16*)&ps8u;
            #pragma unroll
            for (int h = 0; h < 8; h++) {
                float s = __bfloat162float(qk8[h]) + __bfloat162float(cp8[h]) + __bfloat162float(ps8[h]);
                S[(h * 16 + i) * 17 + j] = s * TEMP_INV;
            }
        }
    }
    __syncthreads();

    // Softmax: 128 rows (h,i)
    if (t < 128) {
        float* row = &S[t * 17];
        float m = -1e30f;
        #pragma unroll
        for (int j = 0; j < 16; j++) m = fmaxf(m, row[j]);
        float sum = 0.f;
        #pragma unroll
        for (int j = 0; j < 16; j++) {
            float e = expf(row[j] - m);
            row[j] = e;
            sum += e;
        }
        sinv[t] = 1.f / sum;
    }
    __syncthreads();

    // AV + LN: thread = (h,i) x half-of-d. 32 indep FMA chains, 2 shfls total.
    {
        int hi = t >> 1;              // (h,i)
        int half = t & 1;
        int d0 = half * 32;
        int vrow = (hi & 0x70);       // h*16
        float o[32];
        #pragma unroll
        for (int k = 0; k < 32; k++) o[k] = 0.f;
        const float* srow = &S[hi * 17];
        #pragma unroll
        for (int j = 0; j < 16; j++) {
            float p = srow[j];
            const float4* vr = (const float4*)&sV[(vrow + j) * 68 + d0];
            #pragma unroll
            for (int k = 0; k < 8; k++) {
                float4 v = vr[k];
                o[4 * k + 0] = fmaf(p, v.x, o[4 * k + 0]);
                o[4 * k + 1] = fmaf(p, v.y, o[4 * k + 1]);
                o[4 * k + 2] = fmaf(p, v.z, o[4 * k + 2]);
                o[4 * k + 3] = fmaf(p, v.w, o[4 * k + 3]);
            }
        }
        float inv = sinv[hi];
        float s1 = 0.f, s2 = 0.f;
        #pragma unroll
        for (int k = 0; k < 32; k++) {
            o[k] *= inv;
            s1 += o[k];
            s2 += o[k] * o[k];
        }
        s1 += __shfl_xor_sync(0xffffffff, s1, 1);
        s2 += __shfl_xor_sync(0xffffffff, s2, 1);
        float mu = s1 * (1.f / 64.f);
        float var = s2 * (1.f / 64.f) - mu * mu;
        float rstd = rsqrtf(var + 1e-5f);
        float* orow = &sO[hi * 68 + d0];
        #pragma unroll
        for (int k = 0; k < 8; k++) {
            float4 y;
            y.x = (o[4 * k + 0] - mu) * rstd;
            y.y = (o[4 * k + 1] - mu) * rstd;
            y.z = (o[4 * k + 2] - mu) * rstd;
            y.w = (o[4 * k + 3] - mu) * rstd;
            *(float4*)&orow[4 * k] = y;
        }
    }
    __syncthreads();

    // masked pool: thread = (h, 2 d's)
    {
        int h = t >> 5, l = t & 31;
        int d0 = 2 * l;
        float p0 = 0.f, p1 = 0.f;
        int cnt = 0;
        #pragma unroll
        for (int i = 0; i < 16; i++) {
            if (code[i] == 0) continue;
            cnt++;
            float2 y = *(const float2*)&sO[(h * 16 + i) * 68 + d0];
            p0 += y.x;
            p1 += y.y;
        }
        float inv = 1.f / (float)cnt;
        g_pooled[b * 512 + h * 64 + d0]     = p0 * gamma[d0] * inv + beta[d0];
        g_pooled[b * 512 + h * 64 + d0 + 1] = p1 * gamma[d0 + 1] * inv + beta[d0 + 1];
    }
}

// -------- K6: MLP --------
__global__ __launch_bounds__(128) void mlp_kernel(
    const float* __restrict__ W1, const float* __restrict__ b1,
    const float* __restrict__ W2, const float* __restrict__ b2) {
    __shared__ float sW1[128], sB1[16], sW2[128], sB2[8];
    int tid = threadIdx.x;
    if (tid < 128) { sW1[tid] = W1[tid]; sW2[tid] = W2[tid]; }
    if (tid < 16) sB1[tid] = b1[tid];
    if (tid < 8)  sB2[tid] = b2[tid];
    __syncthreads();
    int b = blockIdx.x * 2 + (tid >> 6);
    int d = tid & 63;
    float hv[8];
    #pragma unroll
    for (int h = 0; h < 8; h++) hv[h] = g_pooled[b * 512 + h * 64 + d];
    float t[16];
    #pragma unroll
    for (int u = 0; u < 16; u++) {
        float a = sB1[u];
        #pragma unroll
        for (int h = 0; h < 8; h++) a = fmaf(hv[h], sW1[h * 16 + u], a);
        t[u] = fmaxf(a, 0.f);
    }
    #pragma unroll
    for (int o = 0; o < 8; o++) {
        float a = sB2[o];
        #pragma unroll
        for (int u = 0; u < 16; u++) a = fmaf(t[u], sW2[u * 8 + o], a);
        g_xflat[b * 512 + d * 8 + o] = a;
    }
}

// -------- K7: word gather + segment mean --------
__global__ void seg_kernel(const int* __restrict__ word_code,
                           const int* __restrict__ n_words,
                           float* __restrict__ out) {
    int n = blockIdx.x;
    int tid = threadIdx.x;
    int off = g_segoff[n];
    int cnt = n_words[n];
    float inv = 1.f / (float)cnt;
    for (int c = tid; c < 512; c += 256) {
        float a = 0.f;
        for (int w = 0; w < cnt; w++) {
            int wc = word_code[off + w];
            a += g_xflat[wc * 512 + c];
        }
        out[n * 512 + c] = a * inv;
    }
}

extern "C" void kernel_launch(void* const* d_in, const int* in_sizes, int n_in,
                              void* d_out, int out_size) {
    const float* char_emb = (const float*)d_in[0];
    const float* Wc       = (const float*)d_in[1];
    const float* bc       = (const float*)d_in[2];
    const float* Wp       = (const float*)d_in[3];
    const float* bp       = (const float*)d_in[4];
    const float* gamma    = (const float*)d_in[5];
    const float* beta     = (const float*)d_in[6];
    const float* W1       = (const float*)d_in[7];
    const float* b1       = (const float*)d_in[8];
    const float* W2       = (const float*)d_in[9];
    const float* b2       = (const float*)d_in[10];
    const int* char_code  = (const int*)d_in[11];
    const int* word_code  = (const int*)d_in[12];
    const int* n_words    = (const int*)d_in[13];
    float* out = (float*)d_out;

    qkv_pos_kernel<<<16, 256>>>(Wp, bp);                    // 1
    qkv_char_kernel<<<256, 256>>>(char_emb, Wc, bc);        // 2
    cppos_kernel<<<257, 128>>>();                           // 3
    charqk_mma_kernel<<<dim3(16, 16, 8), 256>>>();          // 4 <- profiled
    qk_transpose_kernel<<<16384, 256>>>();                  // 5
    seg_scan_kernel<<<1, 256>>>(n_words);                   // 6
    attn_kernel<<<B_SZ, 256>>>(char_code, gamma, beta);     // 7
    mlp_kernel<<<B_SZ / 2, 128>>>(W1, b1, W2, b2);          // 8
    seg_kernel<<<N_NAMES, 256>>>(word_code, n_words, out);  // 9
}

// round 9
// speedup vs baseline: 1.6190x; 1.0124x over previous
#include <cuda_runtime.h>
#include <cuda_bf16.h>
#include <math.h>
#include <cstdint>

#define V_SZ 2048
#define L_SZ 16
#define H_SZ 8
#define D_SZ 64
#define B_SZ 8192
#define NW_TOTAL 8192
#define N_NAMES 2048
#define TEMP_INV 0.125f

// -------- scratch --------
__device__ float g_cq[V_SZ * H_SZ * D_SZ];
__device__ float g_ck[V_SZ * H_SZ * D_SZ];
__device__ float g_cv[V_SZ * H_SZ * D_SZ];
__device__ __nv_bfloat16 g_cqb[V_SZ * 512];
__device__ __nv_bfloat16 g_ckb[V_SZ * 512];
__device__ float g_pq[L_SZ * H_SZ * D_SZ];
__device__ float g_pk[L_SZ * H_SZ * D_SZ];
__device__ float g_pv[L_SZ * H_SZ * D_SZ];
__device__ __nv_bfloat16 g_qkh[H_SZ * V_SZ * V_SZ];   // 67MB [h][x][y]
__device__ __nv_bfloat16 g_qkb[V_SZ * V_SZ * H_SZ];   // 67MB [x][y][h]
__device__ __nv_bfloat16 g_cpb[V_SZ * L_SZ * H_SZ];   // [v][j][h]
__device__ __nv_bfloat16 g_posb[L_SZ * L_SZ * H_SZ];  // [i][j][h]
__device__ float g_pooled[B_SZ * H_SZ * D_SZ];
__device__ float g_xflat[B_SZ * 512];
__device__ int   g_segoff[N_NAMES];

// -------- K1: prep = pos-embed QKV (blocks 0..15) + char QKV (blocks 16..271) --------
__global__ __launch_bounds__(256) void prep_kernel(
    const float* __restrict__ Wp, const float* __restrict__ bp,
    const float* __restrict__ emb, const float* __restrict__ Wc, const float* __restrict__ bc) {
    int tid = threadIdx.x;
    if (blockIdx.x < 16) {
        int l = blockIdx.x;
        __shared__ float sp[64];
        if (tid < 64) {
            int f = tid & 31;
            double inv = pow(10000.0, -(double)f / 32.0);
            double ph = (double)l * inv;
            sp[tid] = (float)((tid < 32) ? cos(ph) : sin(ph));
        }
        __syncthreads();
        for (int c = tid; c < 1536; c += 256) {
            float a = 0.f;
            #pragma unroll 8
            for (int k = 0; k < 64; k++) a += sp[k] * Wp[k * 1536 + c];
            a += bp[c];
            int t = c >> 9, rem = c & 511;
            float* dst = (t == 0) ? g_pq : (t == 1) ? g_pk : g_pv;
            dst[l * 512 + rem] = a;
        }
        return;
    }
    int row0 = (blockIdx.x - 16) * 8;
    __shared__ float se[8][64];
    for (int idx = tid; idx < 512; idx += 256)
        se[idx >> 6][idx & 63] = emb[(row0 + (idx >> 6)) * 64 + (idx & 63)];
    __syncthreads();
    float acc[6][8];
    #pragma unroll
    for (int c = 0; c < 6; c++)
        #pragma unroll
        for (int r = 0; r < 8; r++) acc[c][r] = 0.f;
    for (int k = 0; k < 64; k++) {
        float w[6];
        #pragma unroll
        for (int c = 0; c < 6; c++) w[c] = Wc[k * 1536 + tid + c * 256];
        #pragma unroll
        for (int r = 0; r < 8; r++) {
            float e = se[r][k];
            #pragma unroll
            for (int c = 0; c < 6; c++) acc[c][r] = fmaf(e, w[c], acc[c][r]);
        }
    }
    #pragma unroll
    for (int c = 0; c < 6; c++) {
        int col = tid + c * 256;
        float bias = bc[col];
        int t = col >> 9, rem = col & 511;
        float* dst = (t == 0) ? g_cq : (t == 1) ? g_ck : g_cv;
        __nv_bfloat16* bdst = (t == 0) ? g_cqb : (t == 1) ? g_ckb : (__nv_bfloat16*)0;
        #pragma unroll
        for (int r = 0; r < 8; r++) {
            float val = acc[c][r] + bias;
            int idx = (row0 + r) * 512 + rem;
            dst[idx] = val;
            if (bdst) bdst[idx] = __float2bfloat16(val);
        }
    }
}

// -------- K2: char_qk GEMM via mma.sync bf16 -> bf16 [h][x][y] --------
__global__ __launch_bounds__(256) void charqk_mma_kernel() {
    __shared__ __align__(16) char smem_raw[36864];
    __nv_bfloat16* sA = (__nv_bfloat16*)smem_raw;            // [128][72]
    __nv_bfloat16* sB = sA + 128 * 72;                        // [128][72]

    int t = threadIdx.x;
    int lane = t & 31;
    int w = t >> 5;
    int X0 = blockIdx.x * 128, Y0 = blockIdx.y * 128, h = blockIdx.z;

    {
        int row = t >> 1, half = t & 1;
        const uint4* srcA = (const uint4*)&g_cqb[(size_t)(X0 + row) * 512 + h * 64 + half * 32];
        const uint4* srcB = (const uint4*)&g_ckb[(size_t)(Y0 + row) * 512 + h * 64 + half * 32];
        uint4* dstA = (uint4*)&sA[row * 72 + half * 32];
        uint4* dstB = (uint4*)&sB[row * 72 + half * 32];
        #pragma unroll
        for (int k = 0; k < 4; k++) { dstA[k] = srcA[k]; dstB[k] = srcB[k]; }
    }
    __syncthreads();

    int wx = w >> 2, wy = w & 3;
    float c[4][4][4];
    #pragma unroll
    for (int mi = 0; mi < 4; mi++)
        #pragma unroll
        for (int ni = 0; ni < 4; ni++)
            #pragma unroll
            for (int e = 0; e < 4; e++) c[mi][ni][e] = 0.f;

    int arow = wx * 64 + (lane & 15);
    int acol_off = ((lane >> 4) & 1) * 8;
    int brow_base = wy * 32 + (lane & 7);
    int bcol_off = ((lane >> 3) & 1) * 8;

    #pragma unroll
    for (int k0 = 0; k0 < 64; k0 += 16) {
        unsigned int bfr[4][2];
        #pragma unroll
        for (int ni = 0; ni < 4; ni++) {
            unsigned int baddr = (unsigned int)__cvta_generic_to_shared(
                &sB[(brow_base + ni * 8) * 72 + k0 + bcol_off]);
            asm volatile("ldmatrix.sync.aligned.m8n8.x2.shared.b16 {%0,%1}, [%2];"
                         : "=r"(bfr[ni][0]), "=r"(bfr[ni][1]) : "r"(baddr));
        }
        #pragma unroll
        for (int mi = 0; mi < 4; mi++) {
            unsigned int afr[4];
            unsigned int aaddr = (unsigned int)__cvta_generic_to_shared(
                &sA[(arow + mi * 16) * 72 + k0 + acol_off]);
            asm volatile("ldmatrix.sync.aligned.m8n8.x4.shared.b16 {%0,%1,%2,%3}, [%4];"
                         : "=r"(afr[0]), "=r"(afr[1]), "=r"(afr[2]), "=r"(afr[3]) : "r"(aaddr));
            #pragma unroll
            for (int ni = 0; ni < 4; ni++) {
                asm volatile(
                    "mma.sync.aligned.m16n8k16.row.col.f32.bf16.bf16.f32 "
                    "{%0,%1,%2,%3}, {%4,%5,%6,%7}, {%8,%9}, {%0,%1,%2,%3};"
                    : "+f"(c[mi][ni][0]), "+f"(c[mi][ni][1]), "+f"(c[mi][ni][2]), "+f"(c[mi][ni][3])
                    : "r"(afr[0]), "r"(afr[1]), "r"(afr[2]), "r"(afr[3]),
                      "r"(bfr[ni][0]), "r"(bfr[ni][1]));
            }
        }
    }
    __syncthreads();

    __nv_bfloat16* sOut = (__nv_bfloat16*)smem_raw;
    {
        int r0 = wx * 64 + (lane >> 2);
        int c0 = wy * 32 + (lane & 3) * 2;
        #pragma unroll
        for (int mi = 0; mi < 4; mi++)
            #pragma unroll
            for (int ni = 0; ni < 4; ni++) {
                int rr = r0 + mi * 16, cc = c0 + ni * 8;
                *(__nv_bfloat162*)&sOut[rr * 136 + cc] =
                    __float22bfloat162_rn(make_float2(c[mi][ni][0], c[mi][ni][1]));
                *(__nv_bfloat162*)&sOut[(rr + 8) * 136 + cc] =
                    __float22bfloat162_rn(make_float2(c[mi][ni][2], c[mi][ni][3]));
            }
    }
    __syncthreads();
    for (int idx = t; idx < 2048; idx += 256) {
        int row = idx >> 4, c16 = (idx & 15) * 8;
        uint4 v = *(uint4*)&sOut[row * 136 + c16];
        *(uint4*)&g_qkh[(size_t)h * V_SZ * V_SZ + (size_t)(X0 + row) * V_SZ + Y0 + c16] = v;
    }
}

// -------- K3: transpose (blocks 0..16383) + cp (16384..16511) + posqk (16512) + scan (16513) --------
__global__ __launch_bounds__(256) void transcp_kernel(const int* __restrict__ nw) {
    int t = threadIdx.x;
    int bx = blockIdx.x;
    if (bx < 16384) {
        int x = bx >> 3;
        int y = ((bx & 7) << 8) + t;
        __nv_bfloat16 tmp[8];
        #pragma unroll
        for (int h = 0; h < 8; h++)
            tmp[h] = g_qkh[h * (V_SZ * V_SZ) + x * V_SZ + y];
        *(uint4*)&g_qkb[((size_t)(x * V_SZ + y)) * 8] = *(uint4*)tmp;
        return;
    }
    if (bx < 16512) {
        // cp: 16 v's per block, thread = (v_local, j)
        int v = (bx - 16384) * 16 + (t >> 4);
        int j = t & 15;
        __nv_bfloat16 tmp[8];
        #pragma unroll
        for (int h = 0; h < 8; h++) {
            float d1 = 0.f, d2 = 0.f;
            #pragma unroll
            for (int d = 0; d < 64; d += 4) {
                float4 pk4 = *(const float4*)&g_pk[j * 512 + h * 64 + d];
                float4 pq4 = *(const float4*)&g_pq[j * 512 + h * 64 + d];
                float4 cq4 = *(const float4*)&g_cq[v * 512 + h * 64 + d];
                float4 ck4 = *(const float4*)&g_ck[v * 512 + h * 64 + d];
                d1 += cq4.x * pk4.x + cq4.y * pk4.y + cq4.z * pk4.z + cq4.w * pk4.w;
                d2 += pq4.x * ck4.x + pq4.y * ck4.y + pq4.z * ck4.z + pq4.w * ck4.w;
            }
            tmp[h] = __float2bfloat16(d1 + d2);
        }
        *(uint4*)&g_cpb[(v * 16 + j) * 8] = *(uint4*)tmp;
        return;
    }
    if (bx == 16512) {
        int i = t >> 4, j = t & 15;
        __nv_bfloat16 tmp[8];
        #pragma unroll
        for (int h = 0; h < 8; h++) {
            float a = 0.f;
            #pragma unroll
            for (int d = 0; d < 64; d += 4) {
                float4 q4 = *(const float4*)&g_pq[i * 512 + h * 64 + d];
                float4 k4 = *(const float4*)&g_pk[j * 512 + h * 64 + d];
                a += q4.x * k4.x + q4.y * k4.y + q4.z * k4.z + q4.w * k4.w;
            }
            tmp[h] = __float2bfloat16(a);
        }
        *(uint4*)&g_posb[t * 8] = *(uint4*)tmp;
        return;
    }
    // scan block
    __shared__ int s[N_NAMES];
    __shared__ int csum[32];
    for (int i = t; i < N_NAMES; i += 256) s[i] = nw[i];
    __syncthreads();
    if (t < 32) {
        int a = 0;
        for (int k = 0; k < 64; k++) a += s[t * 64 + k];
        int x = a;
        #pragma unroll
        for (int o = 1; o < 32; o <<= 1) {
            int y = __shfl_up_sync(0xffffffff, x, o);
            if (t >= o) x += y;
        }
        csum[t] = x - a;
    }
    __syncthreads();
    if (t < 32) {
        int off = csum[t];
        for (int k = 0; k < 64; k++) {
            g_segoff[t * 64 + k] = off;
            off += s[t * 64 + k];
        }
    }
}

// -------- K4: attention (block per b, 256 thr, sV reused as sO) --------
__global__ __launch_bounds__(256, 4) void attn_kernel(
    const int* __restrict__ code_g, const float* __restrict__ gamma, const float* __restrict__ beta) {
    __shared__ float sV[8 * 16 * 68];     // [h][p][68]; reused as normalized-output sO
    __shared__ float S[8 * 16 * 17];
    __shared__ float sinv[128];
    __shared__ int code[16];

    int t = threadIdx.x;
    int b = blockIdx.x;

    if (t < 16) code[t] = code_g[b * 16 + t];
    __syncthreads();

    // V gather
    #pragma unroll
    for (int e = t; e < 2048; e += 256) {
        int p = e >> 7, r = e & 127;
        int h = r >> 4, d4 = (r & 15) * 4;
        float4 cv4 = *(const float4*)&g_cv[code[p] * 512 + r * 4];
        float4 pv4 = *(const float4*)&g_pv[p * 512 + r * 4];
        float4 v;
        v.x = cv4.x + pv4.x; v.y = cv4.y + pv4.y; v.z = cv4.z + pv4.z; v.w = cv4.w + pv4.w;
        *(float4*)&sV[(h * 16 + p) * 68 + d4] = v;
    }

    // Score gather: one (i,j) per thread, 8 heads per 16B sector
    {
        int i = t >> 4, j = t & 15;
        int cj = code[j];
        if (cj == 0) {
            #pragma unroll
            for (int h = 0; h < 8; h++) S[(h * 16 + i) * 17 + j] = -1e9f;
        } else {
            int ci = code[i];
            uint4 qk8u = *(const uint4*)&g_qkb[((size_t)((ci << 11) + cj)) * 8];
            uint4 cp8u = *(const uint4*)&g_cpb[((ci << 4) + j) * 8];
            uint4 ps8u = *(const uint4*)&g_posb[((i << 4) + j) * 8];
            const __nv_bfloat16* qk8 = (const __nv_bfloat16*)&qk8u;
            const __nv_bfloat16* cp8 = (const __nv_bfloat16*)&cp8u;
            const __nv_bfloat16* ps8 = (const __nv_bfloat16*)&ps8u;
            #pragma unroll
            for (int h = 0; h < 8; h++) {
                float s = __bfloat162float(qk8[h]) + __bfloat162float(cp8[h]) + __bfloat162float(ps8[h]);
                S[(h * 16 + i) * 17 + j] = s * TEMP_INV;
            }
        }
    }
    __syncthreads();

    // Softmax: 128 rows (h,i)
    if (t < 128) {
        float* row = &S[t * 17];
        float m = -1e30f;
        #pragma unroll
        for (int j = 0; j < 16; j++) m = fmaxf(m, row[j]);
        float sum = 0.f;
        #pragma unroll
        for (int j = 0; j < 16; j++) {
            float e = expf(row[j] - m);
            row[j] = e;
            sum += e;
        }
        sinv[t] = 1.f / sum;
    }
    __syncthreads();

    // AV + LN stats: thread = (h,i) x half-of-d; accumulators in registers.
    float o[32];
    float mu, rstd;
    int hi = t >> 1;
    int half = t & 1;
    int d0 = half * 32;
    {
        int vrow = (hi & 0x70);
        #pragma unroll
        for (int k = 0; k < 32; k++) o[k] = 0.f;
        const float* srow = &S[hi * 17];
        #pragma unroll
        for (int j = 0; j < 16; j++) {
            float p = srow[j];
            const float4* vr = (const float4*)&sV[(vrow + j) * 68 + d0];
            #pragma unroll
            for (int k = 0; k < 8; k++) {
                float4 v = vr[k];
                o[4 * k + 0] = fmaf(p, v.x, o[4 * k + 0]);
                o[4 * k + 1] = fmaf(p, v.y, o[4 * k + 1]);
                o[4 * k + 2] = fmaf(p, v.z, o[4 * k + 2]);
                o[4 * k + 3] = fmaf(p, v.w, o[4 * k + 3]);
            }
        }
        float inv = sinv[hi];
        float s1 = 0.f, s2 = 0.f;
        #pragma unroll
        for (int k = 0; k < 32; k++) {
            o[k] *= inv;
            s1 += o[k];
            s2 += o[k] * o[k];
        }
        s1 += __shfl_xor_sync(0xffffffff, s1, 1);
        s2 += __shfl_xor_sync(0xffffffff, s2, 1);
        mu = s1 * (1.f / 64.f);
        float var = s2 * (1.f / 64.f) - mu * mu;
        rstd = rsqrtf(var + 1e-5f);
    }
    __syncthreads();   // all sV reads complete -> safe to overwrite

    {
        float* orow = &sV[hi * 68 + d0];
        #pragma unroll
        for (int k = 0; k < 8; k++) {
            float4 y;
            y.x = (o[4 * k + 0] - mu) * rstd;
            y.y = (o[4 * k + 1] - mu) * rstd;
            y.z = (o[4 * k + 2] - mu) * rstd;
            y.w = (o[4 * k + 3] - mu) * rstd;
            *(float4*)&orow[4 * k] = y;
        }
    }
    __syncthreads();

    // masked pool: thread = (h, 2 d's)
    {
        int h = t >> 5, l = t & 31;
        int dd = 2 * l;
        float p0 = 0.f, p1 = 0.f;
        int cnt = 0;
        #pragma unroll
        for (int i = 0; i < 16; i++) {
            if (code[i] == 0) continue;
            cnt++;
            float2 y = *(const float2*)&sV[(h * 16 + i) * 68 + dd];
            p0 += y.x;
            p1 += y.y;
        }
        float inv = 1.f / (float)cnt;
        g_pooled[b * 512 + h * 64 + dd]     = p0 * gamma[dd] * inv + beta[dd];
        g_pooled[b * 512 + h * 64 + dd + 1] = p1 * gamma[dd + 1] * inv + beta[dd + 1];
    }
}

// -------- K5: MLP --------
__global__ __launch_bounds__(128) void mlp_kernel(
    const float* __restrict__ W1, const float* __restrict__ b1,
    const float* __restrict__ W2, const float* __restrict__ b2) {
    __shared__ float sW1[128], sB1[16], sW2[128], sB2[8];
    int tid = threadIdx.x;
    if (tid < 128) { sW1[tid] = W1[tid]; sW2[tid] = W2[tid]; }
    if (tid < 16) sB1[tid] = b1[tid];
    if (tid < 8)  sB2[tid] = b2[tid];
    __syncthreads();
    int b = blockIdx.x * 2 + (tid >> 6);
    int d = tid & 63;
    float hv[8];
    #pragma unroll
    for (int h = 0; h < 8; h++) hv[h] = g_pooled[b * 512 + h * 64 + d];
    float t[16];
    #pragma unroll
    for (int u = 0; u < 16; u++) {
        float a = sB1[u];
        #pragma unroll
        for (int h = 0; h < 8; h++) a = fmaf(hv[h], sW1[h * 16 + u], a);
        t[u] = fmaxf(a, 0.f);
    }
    #pragma unroll
    for (int o = 0; o < 8; o++) {
        float a = sB2[o];
        #pragma unroll
        for (int u = 0; u < 16; u++) a = fmaf(t[u], sW2[u * 8 + o], a);
        g_xflat[b * 512 + d * 8 + o] = a;
    }
}

// -------- K6: word gather + segment mean --------
__global__ void seg_kernel(const int* __restrict__ word_code,
                           const int* __restrict__ n_words,
                           float* __restrict__ out) {
    int n = blockIdx.x;
    int tid = threadIdx.x;
    int off = g_segoff[n];
    int cnt = n_words[n];
    float inv = 1.f / (float)cnt;
    for (int c = tid; c < 512; c += 256) {
        float a = 0.f;
        for (int w = 0; w < cnt; w++) {
            int wc = word_code[off + w];
            a += g_xflat[wc * 512 + c];
        }
        out[n * 512 + c] = a * inv;
    }
}

extern "C" void kernel_launch(void* const* d_in, const int* in_sizes, int n_in,
                              void* d_out, int out_size) {
    const float* char_emb = (const float*)d_in[0];
    const float* Wc       = (const float*)d_in[1];
    const float* bc       = (const float*)d_in[2];
    const float* Wp       = (const float*)d_in[3];
    const float* bp       = (const float*)d_in[4];
    const float* gamma    = (const float*)d_in[5];
    const float* beta     = (const float*)d_in[6];
    const float* W1       = (const float*)d_in[7];
    const float* b1       = (const float*)d_in[8];
    const float* W2       = (const float*)d_in[9];
    const float* b2       = (const float*)d_in[10];
    const int* char_code  = (const int*)d_in[11];
    const int* word_code  = (const int*)d_in[12];
    const int* n_words    = (const int*)d_in[13];
    float* out = (float*)d_out;

    prep_kernel<<<272, 256>>>(Wp, bp, char_emb, Wc, bc);     // 1
    charqk_mma_kernel<<<dim3(16, 16, 8), 256>>>();           // 2
    transcp_kernel<<<16514, 256>>>(n_words);                 // 3
    attn_kernel<<<B_SZ, 256>>>(char_code, gamma, beta);      // 4 <- profiled
    mlp_kernel<<<B_SZ / 2, 128>>>(W1, b1, W2, b2);           // 5
    seg_kernel<<<N_NAMES, 256>>>(word_code, n_words, out);   // 6
}

// round 10
// speedup vs baseline: 2.0019x; 1.2366x over previous
#include <cuda_runtime.h>
#include <cuda_bf16.h>
#include <math.h>
#include <cstdint>

#define V_SZ 2048
#define L_SZ 16
#define H_SZ 8
#define D_SZ 64
#define B_SZ 8192
#define NW_TOTAL 8192
#define N_NAMES 2048
#define TEMP_INV 0.125f

// -------- scratch --------
__device__ float g_cq[V_SZ * H_SZ * D_SZ];
__device__ float g_ck[V_SZ * H_SZ * D_SZ];
__device__ float g_cv[V_SZ * H_SZ * D_SZ];
__device__ __nv_bfloat16 g_cqb[V_SZ * 512];
__device__ __nv_bfloat16 g_ckb[V_SZ * 512];
__device__ float g_pq[L_SZ * H_SZ * D_SZ];
__device__ float g_pk[L_SZ * H_SZ * D_SZ];
__device__ float g_pv[L_SZ * H_SZ * D_SZ];
__device__ __nv_bfloat16 g_qkh[H_SZ * V_SZ * V_SZ];   // 67MB [h][x][y]
__device__ __nv_bfloat16 g_qkb[V_SZ * V_SZ * H_SZ];   // 67MB [x][y][h]
__device__ __nv_bfloat16 g_cpb[V_SZ * L_SZ * H_SZ];   // [v][j][h]
__device__ __nv_bfloat16 g_posb[L_SZ * L_SZ * H_SZ];  // [i][j][h]
__device__ float g_pooled[B_SZ * H_SZ * D_SZ];
__device__ float g_xflat[B_SZ * 512];
__device__ int   g_segoff[N_NAMES];

// -------- K1: prep = pos-embed QKV (blocks 0..15) + char QKV (blocks 16..271) --------
__global__ __launch_bounds__(256) void prep_kernel(
    const float* __restrict__ Wp, const float* __restrict__ bp,
    const float* __restrict__ emb, const float* __restrict__ Wc, const float* __restrict__ bc) {
    int tid = threadIdx.x;
    if (blockIdx.x < 16) {
        int l = blockIdx.x;
        __shared__ float sp[64];
        if (tid < 64) {
            int f = tid & 31;
            double inv = pow(10000.0, -(double)f / 32.0);
            double ph = (double)l * inv;
            sp[tid] = (float)((tid < 32) ? cos(ph) : sin(ph));
        }
        __syncthreads();
        for (int c = tid; c < 1536; c += 256) {
            float a = 0.f;
            #pragma unroll 8
            for (int k = 0; k < 64; k++) a += sp[k] * Wp[k * 1536 + c];
            a += bp[c];
            int t = c >> 9, rem = c & 511;
            float* dst = (t == 0) ? g_pq : (t == 1) ? g_pk : g_pv;
            dst[l * 512 + rem] = a;
        }
        return;
    }
    int row0 = (blockIdx.x - 16) * 8;
    __shared__ float se[8][64];
    for (int idx = tid; idx < 512; idx += 256)
        se[idx >> 6][idx & 63] = emb[(row0 + (idx >> 6)) * 64 + (idx & 63)];
    __syncthreads();
    float acc[6][8];
    #pragma unroll
    for (int c = 0; c < 6; c++)
        #pragma unroll
        for (int r = 0; r < 8; r++) acc[c][r] = 0.f;
    for (int k = 0; k < 64; k++) {
        float w[6];
        #pragma unroll
        for (int c = 0; c < 6; c++) w[c] = Wc[k * 1536 + tid + c * 256];
        #pragma unroll
        for (int r = 0; r < 8; r++) {
            float e = se[r][k];
            #pragma unroll
            for (int c = 0; c < 6; c++) acc[c][r] = fmaf(e, w[c], acc[c][r]);
        }
    }
    #pragma unroll
    for (int c = 0; c < 6; c++) {
        int col = tid + c * 256;
        float bias = bc[col];
        int t = col >> 9, rem = col & 511;
        float* dst = (t == 0) ? g_cq : (t == 1) ? g_ck : g_cv;
        __nv_bfloat16* bdst = (t == 0) ? g_cqb : (t == 1) ? g_ckb : (__nv_bfloat16*)0;
        #pragma unroll
        for (int r = 0; r < 8; r++) {
            float val = acc[c][r] + bias;
            int idx = (row0 + r) * 512 + rem;
            dst[idx] = val;
            if (bdst) bdst[idx] = __float2bfloat16(val);
        }
    }
}

// -------- K2: char_qk GEMM via mma.sync bf16 -> bf16 [h][x][y] --------
__global__ __launch_bounds__(256) void charqk_mma_kernel() {
    __shared__ __align__(16) char smem_raw[36864];
    __nv_bfloat16* sA = (__nv_bfloat16*)smem_raw;            // [128][72]
    __nv_bfloat16* sB = sA + 128 * 72;                        // [128][72]

    int t = threadIdx.x;
    int lane = t & 31;
    int w = t >> 5;
    int X0 = blockIdx.x * 128, Y0 = blockIdx.y * 128, h = blockIdx.z;

    {
        int row = t >> 1, half = t & 1;
        const uint4* srcA = (const uint4*)&g_cqb[(size_t)(X0 + row) * 512 + h * 64 + half * 32];
        const uint4* srcB = (const uint4*)&g_ckb[(size_t)(Y0 + row) * 512 + h * 64 + half * 32];
        uint4* dstA = (uint4*)&sA[row * 72 + half * 32];
        uint4* dstB = (uint4*)&sB[row * 72 + half * 32];
        #pragma unroll
        for (int k = 0; k < 4; k++) { dstA[k] = srcA[k]; dstB[k] = srcB[k]; }
    }
    __syncthreads();

    int wx = w >> 2, wy = w & 3;
    float c[4][4][4];
    #pragma unroll
    for (int mi = 0; mi < 4; mi++)
        #pragma unroll
        for (int ni = 0; ni < 4; ni++)
            #pragma unroll
            for (int e = 0; e < 4; e++) c[mi][ni][e] = 0.f;

    int arow = wx * 64 + (lane & 15);
    int acol_off = ((lane >> 4) & 1) * 8;
    int brow_base = wy * 32 + (lane & 7);
    int bcol_off = ((lane >> 3) & 1) * 8;

    #pragma unroll
    for (int k0 = 0; k0 < 64; k0 += 16) {
        unsigned int bfr[4][2];
        #pragma unroll
        for (int ni = 0; ni < 4; ni++) {
            unsigned int baddr = (unsigned int)__cvta_generic_to_shared(
                &sB[(brow_base + ni * 8) * 72 + k0 + bcol_off]);
            asm volatile("ldmatrix.sync.aligned.m8n8.x2.shared.b16 {%0,%1}, [%2];"
                         : "=r"(bfr[ni][0]), "=r"(bfr[ni][1]) : "r"(baddr));
        }
        #pragma unroll
        for (int mi = 0; mi < 4; mi++) {
            unsigned int afr[4];
            unsigned int aaddr = (unsigned int)__cvta_generic_to_shared(
                &sA[(arow + mi * 16) * 72 + k0 + acol_off]);
            asm volatile("ldmatrix.sync.aligned.m8n8.x4.shared.b16 {%0,%1,%2,%3}, [%4];"
                         : "=r"(afr[0]), "=r"(afr[1]), "=r"(afr[2]), "=r"(afr[3]) : "r"(aaddr));
            #pragma unroll
            for (int ni = 0; ni < 4; ni++) {
                asm volatile(
                    "mma.sync.aligned.m16n8k16.row.col.f32.bf16.bf16.f32 "
                    "{%0,%1,%2,%3}, {%4,%5,%6,%7}, {%8,%9}, {%0,%1,%2,%3};"
                    : "+f"(c[mi][ni][0]), "+f"(c[mi][ni][1]), "+f"(c[mi][ni][2]), "+f"(c[mi][ni][3])
                    : "r"(afr[0]), "r"(afr[1]), "r"(afr[2]), "r"(afr[3]),
                      "r"(bfr[ni][0]), "r"(bfr[ni][1]));
            }
        }
    }
    __syncthreads();

    __nv_bfloat16* sOut = (__nv_bfloat16*)smem_raw;
    {
        int r0 = wx * 64 + (lane >> 2);
        int c0 = wy * 32 + (lane & 3) * 2;
        #pragma unroll
        for (int mi = 0; mi < 4; mi++)
            #pragma unroll
            for (int ni = 0; ni < 4; ni++) {
                int rr = r0 + mi * 16, cc = c0 + ni * 8;
                *(__nv_bfloat162*)&sOut[rr * 136 + cc] =
                    __float22bfloat162_rn(make_float2(c[mi][ni][0], c[mi][ni][1]));
                *(__nv_bfloat162*)&sOut[(rr + 8) * 136 + cc] =
                    __float22bfloat162_rn(make_float2(c[mi][ni][2], c[mi][ni][3]));
            }
    }
    __syncthreads();
    for (int idx = t; idx < 2048; idx += 256) {
        int row = idx >> 4, c16 = (idx & 15) * 8;
        uint4 v = *(uint4*)&sOut[row * 136 + c16];
        *(uint4*)&g_qkh[(size_t)h * V_SZ * V_SZ + (size_t)(X0 + row) * V_SZ + Y0 + c16] = v;
    }
}

// -------- K3: scan(bx0) + posqk(bx1) + cp(bx 2..2049) + transpose(bx 2050..18433) --------
// slow/small blocks FIRST so they overlap the transpose wave instead of tailing it
__global__ __launch_bounds__(256) void transcp_kernel(const int* __restrict__ nw) {
    int t = threadIdx.x;
    int bx = blockIdx.x;
    if (bx >= 2050) {
        int e = bx - 2050;
        int x = e >> 3;
        int y = ((e & 7) << 8) + t;
        __nv_bfloat16 tmp[8];
        #pragma unroll
        for (int h = 0; h < 8; h++)
            tmp[h] = g_qkh[h * (V_SZ * V_SZ) + x * V_SZ + y];
        *(uint4*)&g_qkb[((size_t)(x * V_SZ + y)) * 8] = *(uint4*)tmp;
        return;
    }
    if (bx >= 2) {
        // cp: one v per block. thread = (h, j, half-of-d)
        int v = bx - 2;
        __shared__ float scq[512], sck[512];
        if (t < 128) *(float4*)&scq[t * 4] = *(const float4*)&g_cq[v * 512 + t * 4];
        else         *(float4*)&sck[(t - 128) * 4] = *(const float4*)&g_ck[v * 512 + (t - 128) * 4];
        __syncthreads();
        int hj = t >> 1, half = t & 1;
        int h = hj >> 4, j = hj & 15;
        int off = j * 512 + h * 64 + half * 32;
        const float4* pk4 = (const float4*)&g_pk[off];
        const float4* pq4 = (const float4*)&g_pq[off];
        const float4* cq4 = (const float4*)&scq[h * 64 + half * 32];
        const float4* ck4 = (const float4*)&sck[h * 64 + half * 32];
        float acc = 0.f;
        #pragma unroll
        for (int k = 0; k < 8; k++) {
            float4 a = pk4[k], b = pq4[k], q = cq4[k], c = ck4[k];
            acc += q.x * a.x + q.y * a.y + q.z * a.z + q.w * a.w
                 + b.x * c.x + b.y * c.y + b.z * c.z + b.w * c.w;
        }
        acc += __shfl_xor_sync(0xffffffff, acc, 1);
        if (!half) g_cpb[(v * 16 + j) * 8 + h] = __float2bfloat16(acc);
        return;
    }
    if (bx == 1) {
        int i = t >> 4, j = t & 15;
        __nv_bfloat16 tmp[8];
        #pragma unroll
        for (int h = 0; h < 8; h++) {
            float a = 0.f;
            #pragma unroll
            for (int d = 0; d < 64; d += 4) {
                float4 q4 = *(const float4*)&g_pq[i * 512 + h * 64 + d];
                float4 k4 = *(const float4*)&g_pk[j * 512 + h * 64 + d];
                a += q4.x * k4.x + q4.y * k4.y + q4.z * k4.z + q4.w * k4.w;
            }
            tmp[h] = __float2bfloat16(a);
        }
        *(uint4*)&g_posb[t * 8] = *(uint4*)tmp;
        return;
    }
    // bx == 0: scan
    __shared__ int s[N_NAMES];
    __shared__ int csum[32];
    for (int i = t; i < N_NAMES; i += 256) s[i] = nw[i];
    __syncthreads();
    if (t < 32) {
        int a = 0;
        for (int k = 0; k < 64; k++) a += s[t * 64 + k];
        int x = a;
        #pragma unroll
        for (int o = 1; o < 32; o <<= 1) {
            int y = __shfl_up_sync(0xffffffff, x, o);
            if (t >= o) x += y;
        }
        csum[t] = x - a;
    }
    __syncthreads();
    if (t < 32) {
        int off = csum[t];
        for (int k = 0; k < 64; k++) {
            g_segoff[t * 64 + k] = off;
            off += s[t * 64 + k];
        }
    }
}

// -------- K4: attention (block per b, 256 thr, sV reused as sO) --------
__global__ __launch_bounds__(256, 4) void attn_kernel(
    const int* __restrict__ code_g, const float* __restrict__ gamma, const float* __restrict__ beta) {
    __shared__ float sV[8 * 16 * 68];     // [h][p][68]; reused as normalized-output sO
    __shared__ float S[8 * 16 * 17];
    __shared__ float sinv[128];
    __shared__ int code[16];

    int t = threadIdx.x;
    int b = blockIdx.x;

    if (t < 16) code[t] = code_g[b * 16 + t];
    __syncthreads();

    // V gather
    #pragma unroll
    for (int e = t; e < 2048; e += 256) {
        int p = e >> 7, r = e & 127;
        int h = r >> 4, d4 = (r & 15) * 4;
        float4 cv4 = *(const float4*)&g_cv[code[p] * 512 + r * 4];
        float4 pv4 = *(const float4*)&g_pv[p * 512 + r * 4];
        float4 v;
        v.x = cv4.x + pv4.x; v.y = cv4.y + pv4.y; v.z = cv4.z + pv4.z; v.w = cv4.w + pv4.w;
        *(float4*)&sV[(h * 16 + p) * 68 + d4] = v;
    }

    // Score gather: one (i,j) per thread, 8 heads per 16B sector
    {
        int i = t >> 4, j = t & 15;
        int cj = code[j];
        if (cj == 0) {
            #pragma unroll
            for (int h = 0; h < 8; h++) S[(h * 16 + i) * 17 + j] = -1e9f;
        } else {
            int ci = code[i];
            uint4 qk8u = *(const uint4*)&g_qkb[((size_t)((ci << 11) + cj)) * 8];
            uint4 cp8u = *(const uint4*)&g_cpb[((ci << 4) + j) * 8];
            uint4 ps8u = *(const uint4*)&g_posb[((i << 4) + j) * 8];
            const __nv_bfloat16* qk8 = (const __nv_bfloat16*)&qk8u;
            const __nv_bfloat16* cp8 = (const __nv_bfloat16*)&cp8u;
            const __nv_bfloat16* ps8 = (const __nv_bfloat16*)&ps8u;
            #pragma unroll
            for (int h = 0; h < 8; h++) {
                float s = __bfloat162float(qk8[h]) + __bfloat162float(cp8[h]) + __bfloat162float(ps8[h]);
                S[(h * 16 + i) * 17 + j] = s * TEMP_INV;
            }
        }
    }
    __syncthreads();

    // Softmax: 128 rows (h,i)
    if (t < 128) {
        float* row = &S[t * 17];
        float m = -1e30f;
        #pragma unroll
        for (int j = 0; j < 16; j++) m = fmaxf(m, row[j]);
        float sum = 0.f;
        #pragma unroll
        for (int j = 0; j < 16; j++) {
            float e = expf(row[j] - m);
            row[j] = e;
            sum += e;
        }
        sinv[t] = 1.f / sum;
    }
    __syncthreads();

    // AV + LN stats: thread = (h,i) x half-of-d; accumulators in registers.
    float o[32];
    float mu, rstd;
    int hi = t >> 1;
    int half = t & 1;
    int d0 = half * 32;
    {
        int vrow = (hi & 0x70);
        #pragma unroll
        for (int k = 0; k < 32; k++) o[k] = 0.f;
        // preload S row via 4 x LDS.128
        float sr[16];
        {
            const float4* s4 = (const float4*)&S[hi * 17];  // row base 68B-aligned? 17 floats*4=68 -> 4B aligned only
            // 17-float stride breaks float4 alignment for odd rows; use scalar-safe path:
        }
        #pragma unroll
        for (int j4 = 0; j4 < 16; j4 += 4) {
            sr[j4 + 0] = S[hi * 17 + j4 + 0];
            sr[j4 + 1] = S[hi * 17 + j4 + 1];
            sr[j4 + 2] = S[hi * 17 + j4 + 2];
            sr[j4 + 3] = S[hi * 17 + j4 + 3];
        }
        #pragma unroll
        for (int j = 0; j < 16; j++) {
            float p = sr[j];
            const float4* vr = (const float4*)&sV[(vrow + j) * 68 + d0];
            #pragma unroll
            for (int k = 0; k < 8; k++) {
                float4 v = vr[k];
                o[4 * k + 0] = fmaf(p, v.x, o[4 * k + 0]);
                o[4 * k + 1] = fmaf(p, v.y, o[4 * k + 1]);
                o[4 * k + 2] = fmaf(p, v.z, o[4 * k + 2]);
                o[4 * k + 3] = fmaf(p, v.w, o[4 * k + 3]);
            }
        }
        float inv = sinv[hi];
        float s1 = 0.f, s2 = 0.f;
        #pragma unroll
        for (int k = 0; k < 32; k++) {
            o[k] *= inv;
            s1 += o[k];
            s2 += o[k] * o[k];
        }
        s1 += __shfl_xor_sync(0xffffffff, s1, 1);
        s2 += __shfl_xor_sync(0xffffffff, s2, 1);
        mu = s1 * (1.f / 64.f);
        float var = s2 * (1.f / 64.f) - mu * mu;
        rstd = rsqrtf(var + 1e-5f);
    }
    __syncthreads();   // all sV reads complete -> safe to overwrite

    {
        float* orow = &sV[hi * 68 + d0];
        #pragma unroll
        for (int k = 0; k < 8; k++) {
            float4 y;
            y.x = (o[4 * k + 0] - mu) * rstd;
            y.y = (o[4 * k + 1] - mu) * rstd;
            y.z = (o[4 * k + 2] - mu) * rstd;
            y.w = (o[4 * k + 3] - mu) * rstd;
            *(float4*)&orow[4 * k] = y;
        }
    }
    __syncthreads();

    // masked pool: thread = (h, 2 d's)
    {
        int h = t >> 5, l = t & 31;
        int dd = 2 * l;
        float p0 = 0.f, p1 = 0.f;
        int cnt = 0;
        #pragma unroll
        for (int i = 0; i < 16; i++) {
            if (code[i] == 0) continue;
            cnt++;
            float2 y = *(const float2*)&sV[(h * 16 + i) * 68 + dd];
            p0 += y.x;
            p1 += y.y;
        }
        float inv = 1.f / (float)cnt;
        g_pooled[b * 512 + h * 64 + dd]     = p0 * gamma[dd] * inv + beta[dd];
        g_pooled[b * 512 + h * 64 + dd + 1] = p1 * gamma[dd + 1] * inv + beta[dd + 1];
    }
}

// -------- K5: MLP --------
__global__ __launch_bounds__(128) void mlp_kernel(
    const float* __restrict__ W1, const float* __restrict__ b1,
    const float* __restrict__ W2, const float* __restrict__ b2) {
    __shared__ float sW1[128], sB1[16], sW2[128], sB2[8];
    int tid = threadIdx.x;
    if (tid < 128) { sW1[tid] = W1[tid]; sW2[tid] = W2[tid]; }
    if (tid < 16) sB1[tid] = b1[tid];
    if (tid < 8)  sB2[tid] = b2[tid];
    __syncthreads();
    int b = blockIdx.x * 2 + (tid >> 6);
    int d = tid & 63;
    float hv[8];
    #pragma unroll
    for (int h = 0; h < 8; h++) hv[h] = g_pooled[b * 512 + h * 64 + d];
    float t[16];
    #pragma unroll
    for (int u = 0; u < 16; u++) {
        float a = sB1[u];
        #pragma unroll
        for (int h = 0; h < 8; h++) a = fmaf(hv[h], sW1[h * 16 + u], a);
        t[u] = fmaxf(a, 0.f);
    }
    #pragma unroll
    for (int o = 0; o < 8; o++) {
        float a = sB2[o];
        #pragma unroll
        for (int u = 0; u < 16; u++) a = fmaf(t[u], sW2[u * 8 + o], a);
        g_xflat[b * 512 + d * 8 + o] = a;
    }
}

// -------- K6: word gather + segment mean --------
__global__ void seg_kernel(const int* __restrict__ word_code,
                           const int* __restrict__ n_words,
                           float* __restrict__ out) {
    int n = blockIdx.x;
    int tid = threadIdx.x;
    int off = g_segoff[n];
    int cnt = n_words[n];
    float inv = 1.f / (float)cnt;
    for (int c = tid; c < 512; c += 256) {
        float a = 0.f;
        for (int w = 0; w < cnt; w++) {
            int wc = word_code[off + w];
            a += g_xflat[wc * 512 + c];
        }
        out[n * 512 + c] = a * inv;
    }
}

extern "C" void kernel_launch(void* const* d_in, const int* in_sizes, int n_in,
                              void* d_out, int out_size) {
    const float* char_emb = (const float*)d_in[0];
    const float* Wc       = (const float*)d_in[1];
    const float* bc       = (const float*)d_in[2];
    const float* Wp       = (const float*)d_in[3];
    const float* bp       = (const float*)d_in[4];
    const float* gamma    = (const float*)d_in[5];
    const float* beta     = (const float*)d_in[6];
    const float* W1       = (const float*)d_in[7];
    const float* b1       = (const float*)d_in[8];
    const float* W2       = (const float*)d_in[9];
    const float* b2       = (const float*)d_in[10];
    const int* char_code  = (const int*)d_in[11];
    const int* word_code  = (const int*)d_in[12];
    const int* n_words    = (const int*)d_in[13];
    float* out = (float*)d_out;

    prep_kernel<<<272, 256>>>(Wp, bp, char_emb, Wc, bc);     // 1
    charqk_mma_kernel<<<dim3(16, 16, 8), 256>>>();           // 2
    transcp_kernel<<<18434, 256>>>(n_words);                 // 3
    attn_kernel<<<B_SZ, 256>>>(char_code, gamma, beta);      // 4 <- profiled
    mlp_kernel<<<B_SZ / 2, 128>>>(W1, b1, W2, b2);           // 5
    seg_kernel<<<N_NAMES, 256>>>(word_code, n_words, out);   // 6
}

// round 11
// speedup vs baseline: 2.6159x; 1.3067x over previous
#include <cuda_runtime.h>
#include <cuda_bf16.h>
#include <math.h>
#include <cstdint>

#define V_SZ 2048
#define L_SZ 16
#define H_SZ 8
#define D_SZ 64
#define B_SZ 8192
#define NW_TOTAL 8192
#define N_NAMES 2048
#define TEMP_INV 0.125f

// -------- scratch --------
__device__ float g_cq[V_SZ * H_SZ * D_SZ];
__device__ float g_ck[V_SZ * H_SZ * D_SZ];
__device__ float g_cv[V_SZ * H_SZ * D_SZ];
__device__ __nv_bfloat16 g_cqb[V_SZ * 512];
__device__ __nv_bfloat16 g_ckb[V_SZ * 512];
__device__ float g_pq[L_SZ * H_SZ * D_SZ];
__device__ float g_pk[L_SZ * H_SZ * D_SZ];
__device__ float g_pv[L_SZ * H_SZ * D_SZ];
__device__ __nv_bfloat16 g_qkh[H_SZ * V_SZ * V_SZ];   // 67MB [h][x][y]
__device__ __nv_bfloat16 g_qkb[V_SZ * V_SZ * H_SZ];   // 67MB [x][y][h]
__device__ __nv_bfloat16 g_cpb[V_SZ * L_SZ * H_SZ];   // [v][j][h]
__device__ __nv_bfloat16 g_posb[L_SZ * L_SZ * H_SZ];  // [i][j][h]
__device__ float g_pooled[B_SZ * H_SZ * D_SZ];
__device__ float g_xflat[B_SZ * 512];
__device__ int   g_segoff[N_NAMES];

// -------- K1: prep = pos-embed QKV (blocks 0..15) + char QKV (blocks 16..271) --------
__global__ __launch_bounds__(256) void prep_kernel(
    const float* __restrict__ Wp, const float* __restrict__ bp,
    const float* __restrict__ emb, const float* __restrict__ Wc, const float* __restrict__ bc) {
    int tid = threadIdx.x;
    if (blockIdx.x < 16) {
        int l = blockIdx.x;
        __shared__ float sp[64];
        if (tid < 64) {
            int f = tid & 31;
            double inv = pow(10000.0, -(double)f / 32.0);
            double ph = (double)l * inv;
            sp[tid] = (float)((tid < 32) ? cos(ph) : sin(ph));
        }
        __syncthreads();
        for (int c = tid; c < 1536; c += 256) {
            float a = 0.f;
            #pragma unroll 8
            for (int k = 0; k < 64; k++) a += sp[k] * Wp[k * 1536 + c];
            a += bp[c];
            int t = c >> 9, rem = c & 511;
            float* dst = (t == 0) ? g_pq : (t == 1) ? g_pk : g_pv;
            dst[l * 512 + rem] = a;
        }
        return;
    }
    int row0 = (blockIdx.x - 16) * 8;
    __shared__ float se[8][64];
    for (int idx = tid; idx < 512; idx += 256)
        se[idx >> 6][idx & 63] = emb[(row0 + (idx >> 6)) * 64 + (idx & 63)];
    __syncthreads();
    float acc[6][8];
    #pragma unroll
    for (int c = 0; c < 6; c++)
        #pragma unroll
        for (int r = 0; r < 8; r++) acc[c][r] = 0.f;
    for (int k = 0; k < 64; k++) {
        float w[6];
        #pragma unroll
        for (int c = 0; c < 6; c++) w[c] = Wc[k * 1536 + tid + c * 256];
        #pragma unroll
        for (int r = 0; r < 8; r++) {
            float e = se[r][k];
            #pragma unroll
            for (int c = 0; c < 6; c++) acc[c][r] = fmaf(e, w[c], acc[c][r]);
        }
    }
    #pragma unroll
    for (int c = 0; c < 6; c++) {
        int col = tid + c * 256;
        float bias = bc[col];
        int t = col >> 9, rem = col & 511;
        float* dst = (t == 0) ? g_cq : (t == 1) ? g_ck : g_cv;
        __nv_bfloat16* bdst = (t == 0) ? g_cqb : (t == 1) ? g_ckb : (__nv_bfloat16*)0;
        #pragma unroll
        for (int r = 0; r < 8; r++) {
            float val = acc[c][r] + bias;
            int idx = (row0 + r) * 512 + rem;
            dst[idx] = val;
            if (bdst) bdst[idx] = __float2bfloat16(val);
        }
    }
}

// -------- K2: char_qk GEMM via mma.sync bf16 -> bf16 [h][x][y] --------
__global__ __launch_bounds__(256) void charqk_mma_kernel() {
    __shared__ __align__(16) char smem_raw[36864];
    __nv_bfloat16* sA = (__nv_bfloat16*)smem_raw;            // [128][72]
    __nv_bfloat16* sB = sA + 128 * 72;                        // [128][72]

    int t = threadIdx.x;
    int lane = t & 31;
    int w = t >> 5;
    int X0 = blockIdx.x * 128, Y0 = blockIdx.y * 128, h = blockIdx.z;

    {
        int row = t >> 1, half = t & 1;
        const uint4* srcA = (const uint4*)&g_cqb[(size_t)(X0 + row) * 512 + h * 64 + half * 32];
        const uint4* srcB = (const uint4*)&g_ckb[(size_t)(Y0 + row) * 512 + h * 64 + half * 32];
        uint4* dstA = (uint4*)&sA[row * 72 + half * 32];
        uint4* dstB = (uint4*)&sB[row * 72 + half * 32];
        #pragma unroll
        for (int k = 0; k < 4; k++) { dstA[k] = srcA[k]; dstB[k] = srcB[k]; }
    }
    __syncthreads();

    int wx = w >> 2, wy = w & 3;
    float c[4][4][4];
    #pragma unroll
    for (int mi = 0; mi < 4; mi++)
        #pragma unroll
        for (int ni = 0; ni < 4; ni++)
            #pragma unroll
            for (int e = 0; e < 4; e++) c[mi][ni][e] = 0.f;

    int arow = wx * 64 + (lane & 15);
    int acol_off = ((lane >> 4) & 1) * 8;
    int brow_base = wy * 32 + (lane & 7);
    int bcol_off = ((lane >> 3) & 1) * 8;

    #pragma unroll
    for (int k0 = 0; k0 < 64; k0 += 16) {
        unsigned int bfr[4][2];
        #pragma unroll
        for (int ni = 0; ni < 4; ni++) {
            unsigned int baddr = (unsigned int)__cvta_generic_to_shared(
                &sB[(brow_base + ni * 8) * 72 + k0 + bcol_off]);
            asm volatile("ldmatrix.sync.aligned.m8n8.x2.shared.b16 {%0,%1}, [%2];"
                         : "=r"(bfr[ni][0]), "=r"(bfr[ni][1]) : "r"(baddr));
        }
        #pragma unroll
        for (int mi = 0; mi < 4; mi++) {
            unsigned int afr[4];
            unsigned int aaddr = (unsigned int)__cvta_generic_to_shared(
                &sA[(arow + mi * 16) * 72 + k0 + acol_off]);
            asm volatile("ldmatrix.sync.aligned.m8n8.x4.shared.b16 {%0,%1,%2,%3}, [%4];"
                         : "=r"(afr[0]), "=r"(afr[1]), "=r"(afr[2]), "=r"(afr[3]) : "r"(aaddr));
            #pragma unroll
            for (int ni = 0; ni < 4; ni++) {
                asm volatile(
                    "mma.sync.aligned.m16n8k16.row.col.f32.bf16.bf16.f32 "
                    "{%0,%1,%2,%3}, {%4,%5,%6,%7}, {%8,%9}, {%0,%1,%2,%3};"
                    : "+f"(c[mi][ni][0]), "+f"(c[mi][ni][1]), "+f"(c[mi][ni][2]), "+f"(c[mi][ni][3])
                    : "r"(afr[0]), "r"(afr[1]), "r"(afr[2]), "r"(afr[3]),
                      "r"(bfr[ni][0]), "r"(bfr[ni][1]));
            }
        }
    }
    __syncthreads();

    __nv_bfloat16* sOut = (__nv_bfloat16*)smem_raw;
    {
        int r0 = wx * 64 + (lane >> 2);
        int c0 = wy * 32 + (lane & 3) * 2;
        #pragma unroll
        for (int mi = 0; mi < 4; mi++)
            #pragma unroll
            for (int ni = 0; ni < 4; ni++) {
                int rr = r0 + mi * 16, cc = c0 + ni * 8;
                *(__nv_bfloat162*)&sOut[rr * 136 + cc] =
                    __float22bfloat162_rn(make_float2(c[mi][ni][0], c[mi][ni][1]));
                *(__nv_bfloat162*)&sOut[(rr + 8) * 136 + cc] =
                    __float22bfloat162_rn(make_float2(c[mi][ni][2], c[mi][ni][3]));
            }
    }
    __syncthreads();
    for (int idx = t; idx < 2048; idx += 256) {
        int row = idx >> 4, c16 = (idx & 15) * 8;
        uint4 v = *(uint4*)&sOut[row * 136 + c16];
        *(uint4*)&g_qkh[(size_t)h * V_SZ * V_SZ + (size_t)(X0 + row) * V_SZ + Y0 + c16] = v;
    }
}

// -------- K3: scan(bx0) + posqk(bx1) + cp(bx 2..2049) + transpose(bx 2050..18433) --------
__global__ __launch_bounds__(256) void transcp_kernel(const int* __restrict__ nw) {
    int t = threadIdx.x;
    int bx = blockIdx.x;
    if (bx >= 2050) {
        int e = bx - 2050;
        int x = e >> 3;
        int y = ((e & 7) << 8) + t;
        __nv_bfloat16 tmp[8];
        #pragma unroll
        for (int h = 0; h < 8; h++)
            tmp[h] = g_qkh[h * (V_SZ * V_SZ) + x * V_SZ + y];
        *(uint4*)&g_qkb[((size_t)(x * V_SZ + y)) * 8] = *(uint4*)tmp;
        return;
    }
    if (bx >= 2) {
        int v = bx - 2;
        __shared__ float scq[512], sck[512];
        if (t < 128) *(float4*)&scq[t * 4] = *(const float4*)&g_cq[v * 512 + t * 4];
        else         *(float4*)&sck[(t - 128) * 4] = *(const float4*)&g_ck[v * 512 + (t - 128) * 4];
        __syncthreads();
        int hj = t >> 1, half = t & 1;
        int h = hj >> 4, j = hj & 15;
        int off = j * 512 + h * 64 + half * 32;
        const float4* pk4 = (const float4*)&g_pk[off];
        const float4* pq4 = (const float4*)&g_pq[off];
        const float4* cq4 = (const float4*)&scq[h * 64 + half * 32];
        const float4* ck4 = (const float4*)&sck[h * 64 + half * 32];
        float acc = 0.f;
        #pragma unroll
        for (int k = 0; k < 8; k++) {
            float4 a = pk4[k], b = pq4[k], q = cq4[k], c = ck4[k];
            acc += q.x * a.x + q.y * a.y + q.z * a.z + q.w * a.w
                 + b.x * c.x + b.y * c.y + b.z * c.z + b.w * c.w;
        }
        acc += __shfl_xor_sync(0xffffffff, acc, 1);
        if (!half) g_cpb[(v * 16 + j) * 8 + h] = __float2bfloat16(acc);
        return;
    }
    if (bx == 1) {
        int i = t >> 4, j = t & 15;
        __nv_bfloat16 tmp[8];
        #pragma unroll
        for (int h = 0; h < 8; h++) {
            float a = 0.f;
            #pragma unroll
            for (int d = 0; d < 64; d += 4) {
                float4 q4 = *(const float4*)&g_pq[i * 512 + h * 64 + d];
                float4 k4 = *(const float4*)&g_pk[j * 512 + h * 64 + d];
                a += q4.x * k4.x + q4.y * k4.y + q4.z * k4.z + q4.w * k4.w;
            }
            tmp[h] = __float2bfloat16(a);
        }
        *(uint4*)&g_posb[t * 8] = *(uint4*)tmp;
        return;
    }
    __shared__ int s[N_NAMES];
    __shared__ int csum[32];
    for (int i = t; i < N_NAMES; i += 256) s[i] = nw[i];
    __syncthreads();
    if (t < 32) {
        int a = 0;
        for (int k = 0; k < 64; k++) a += s[t * 64 + k];
        int x = a;
        #pragma unroll
        for (int o = 1; o < 32; o <<= 1) {
            int y = __shfl_up_sync(0xffffffff, x, o);
            if (t >= o) x += y;
        }
        csum[t] = x - a;
    }
    __syncthreads();
    if (t < 32) {
        int off = csum[t];
        for (int k = 0; k < 64; k++) {
            g_segoff[t * 64 + k] = off;
            off += s[t * 64 + k];
        }
    }
}

// -------- K4: attention. warp=head AV; LN+pool in registers via shuffles --------
__global__ __launch_bounds__(256, 4) void attn_kernel(
    const int* __restrict__ code_g, const float* __restrict__ gamma, const float* __restrict__ beta) {
    __shared__ float sV[8 * 16 * 68];     // [h][p][68]
    __shared__ float S[8 * 16 * 17];      // normalized probs after softmax
    __shared__ int code[16];

    int t = threadIdx.x;
    int b = blockIdx.x;

    if (t < 16) code[t] = code_g[b * 16 + t];
    __syncthreads();

    // V gather
    #pragma unroll
    for (int e = t; e < 2048; e += 256) {
        int p = e >> 7, r = e & 127;
        float4 cv4 = *(const float4*)&g_cv[code[p] * 512 + r * 4];
        float4 pv4 = *(const float4*)&g_pv[p * 512 + r * 4];
        float4 v;
        v.x = cv4.x + pv4.x; v.y = cv4.y + pv4.y; v.z = cv4.z + pv4.z; v.w = cv4.w + pv4.w;
        int h = r >> 4, d4 = (r & 15) * 4;
        *(float4*)&sV[(h * 16 + p) * 68 + d4] = v;
    }

    // Score gather: one (i,j) per thread, 8 heads per 16B sector
    {
        int i = t >> 4, j = t & 15;
        int cj = code[j];
        if (cj == 0) {
            #pragma unroll
            for (int h = 0; h < 8; h++) S[(h * 16 + i) * 17 + j] = -1e9f;
        } else {
            int ci = code[i];
            uint4 qk8u = *(const uint4*)&g_qkb[((size_t)((ci << 11) + cj)) * 8];
            uint4 cp8u = *(const uint4*)&g_cpb[((ci << 4) + j) * 8];
            uint4 ps8u = *(const uint4*)&g_posb[((i << 4) + j) * 8];
            const __nv_bfloat16* qk8 = (const __nv_bfloat16*)&qk8u;
            const __nv_bfloat16* cp8 = (const __nv_bfloat16*)&cp8u;
            const __nv_bfloat16* ps8 = (const __nv_bfloat16*)&ps8u;
            #pragma unroll
            for (int h = 0; h < 8; h++) {
                float s = __bfloat162float(qk8[h]) + __bfloat162float(cp8[h]) + __bfloat162float(ps8[h]);
                S[(h * 16 + i) * 17 + j] = s * TEMP_INV;
            }
        }
    }
    __syncthreads();

    // Softmax: 128 rows; store NORMALIZED probabilities
    if (t < 128) {
        float* row = &S[t * 17];
        float m = -1e30f;
        #pragma unroll
        for (int j = 0; j < 16; j++) m = fmaxf(m, row[j]);
        float sum = 0.f;
        float e[16];
        #pragma unroll
        for (int j = 0; j < 16; j++) {
            e[j] = expf(row[j] - m);
            sum += e[j];
        }
        float inv = 1.f / sum;
        #pragma unroll
        for (int j = 0; j < 16; j++) row[j] = e[j] * inv;
    }
    __syncthreads();

    // AV + LN + pool: warp = head. lane = (i0 = l>>3, dg = l&7).
    // lane owns rows i0*4..i0*4+3, d-chunks {4dg..4dg+3} and {32+4dg..32+4dg+3}.
    {
        int h = t >> 5;
        int lane = t & 31;
        int i0 = lane >> 3;
        int dg = lane & 7;

        float o[4][8];
        #pragma unroll
        for (int ii = 0; ii < 4; ii++)
            #pragma unroll
            for (int k = 0; k < 8; k++) o[ii][k] = 0.f;

        const float* Sbase = &S[(h * 16 + i0 * 4) * 17];
        const float* Vbase = &sV[(h * 16) * 68];
        #pragma unroll
        for (int j = 0; j < 16; j++) {
            float4 vA = *(const float4*)&Vbase[j * 68 + dg * 4];
            float4 vB = *(const float4*)&Vbase[j * 68 + 32 + dg * 4];
            #pragma unroll
            for (int ii = 0; ii < 4; ii++) {
                float p = Sbase[ii * 17 + j];
                o[ii][0] = fmaf(p, vA.x, o[ii][0]);
                o[ii][1] = fmaf(p, vA.y, o[ii][1]);
                o[ii][2] = fmaf(p, vA.z, o[ii][2]);
                o[ii][3] = fmaf(p, vA.w, o[ii][3]);
                o[ii][4] = fmaf(p, vB.x, o[ii][4]);
                o[ii][5] = fmaf(p, vB.y, o[ii][5]);
                o[ii][6] = fmaf(p, vB.z, o[ii][6]);
                o[ii][7] = fmaf(p, vB.w, o[ii][7]);
            }
        }

        // LayerNorm per row: reduce across the 8 dg-lanes (shfl_xor 1,2,4)
        #pragma unroll
        for (int ii = 0; ii < 4; ii++) {
            float s1 = 0.f, s2 = 0.f;
            #pragma unroll
            for (int k = 0; k < 8; k++) { s1 += o[ii][k]; s2 += o[ii][k] * o[ii][k]; }
            s1 += __shfl_xor_sync(0xffffffff, s1, 1);
            s2 += __shfl_xor_sync(0xffffffff, s2, 1);
            s1 += __shfl_xor_sync(0xffffffff, s1, 2);
            s2 += __shfl_xor_sync(0xffffffff, s2, 2);
            s1 += __shfl_xor_sync(0xffffffff, s1, 4);
            s2 += __shfl_xor_sync(0xffffffff, s2, 4);
            float mu = s1 * (1.f / 64.f);
            float var = s2 * (1.f / 64.f) - mu * mu;
            float rstd = rsqrtf(var + 1e-5f);
            #pragma unroll
            for (int k = 0; k < 8; k++) o[ii][k] = (o[ii][k] - mu) * rstd;
        }

        // masked pool over rows: thread-local 4 rows, then shfl_xor 8,16 across i-groups
        float pl[8];
        #pragma unroll
        for (int k = 0; k < 8; k++) pl[k] = 0.f;
        float cntf = 0.f;
        #pragma unroll
        for (int ii = 0; ii < 4; ii++) {
            if (code[i0 * 4 + ii] != 0) {
                cntf += 1.f;
                #pragma unroll
                for (int k = 0; k < 8; k++) pl[k] += o[ii][k];
            }
        }
        #pragma unroll
        for (int k = 0; k < 8; k++) {
            pl[k] += __shfl_xor_sync(0xffffffff, pl[k], 8);
            pl[k] += __shfl_xor_sync(0xffffffff, pl[k], 16);
        }
        cntf += __shfl_xor_sync(0xffffffff, cntf, 8);
        cntf += __shfl_xor_sync(0xffffffff, cntf, 16);

        if (i0 == 0) {
            float inv = 1.f / cntf;
            float4 gA = *(const float4*)&gamma[dg * 4];
            float4 gB = *(const float4*)&gamma[32 + dg * 4];
            float4 bA = *(const float4*)&beta[dg * 4];
            float4 bB = *(const float4*)&beta[32 + dg * 4];
            float* dst = &g_pooled[b * 512 + h * 64];
            float4 wA, wB;
            wA.x = pl[0] * gA.x * inv + bA.x;
            wA.y = pl[1] * gA.y * inv + bA.y;
            wA.z = pl[2] * gA.z * inv + bA.z;
            wA.w = pl[3] * gA.w * inv + bA.w;
            wB.x = pl[4] * gB.x * inv + bB.x;
            wB.y = pl[5] * gB.y * inv + bB.y;
            wB.z = pl[6] * gB.z * inv + bB.z;
            wB.w = pl[7] * gB.w * inv + bB.w;
            *(float4*)&dst[dg * 4] = wA;
            *(float4*)&dst[32 + dg * 4] = wB;
        }
    }
}

// -------- K5: MLP --------
__global__ __launch_bounds__(128) void mlp_kernel(
    const float* __restrict__ W1, const float* __restrict__ b1,
    const float* __restrict__ W2, const float* __restrict__ b2) {
    __shared__ float sW1[128], sB1[16], sW2[128], sB2[8];
    int tid = threadIdx.x;
    if (tid < 128) { sW1[tid] = W1[tid]; sW2[tid] = W2[tid]; }
    if (tid < 16) sB1[tid] = b1[tid];
    if (tid < 8)  sB2[tid] = b2[tid];
    __syncthreads();
    int b = blockIdx.x * 2 + (tid >> 6);
    int d = tid & 63;
    float hv[8];
    #pragma unroll
    for (int h = 0; h < 8; h++) hv[h] = g_pooled[b * 512 + h * 64 + d];
    float t[16];
    #pragma unroll
    for (int u = 0; u < 16; u++) {
        float a = sB1[u];
        #pragma unroll
        for (int h = 0; h < 8; h++) a = fmaf(hv[h], sW1[h * 16 + u], a);
        t[u] = fmaxf(a, 0.f);
    }
    #pragma unroll
    for (int o = 0; o < 8; o++) {
        float a = sB2[o];
        #pragma unroll
        for (int u = 0; u < 16; u++) a = fmaf(t[u], sW2[u * 8 + o], a);
        g_xflat[b * 512 + d * 8 + o] = a;
    }
}

// -------- K6: word gather + segment mean --------
__global__ void seg_kernel(const int* __restrict__ word_code,
                           const int* __restrict__ n_words,
                           float* __restrict__ out) {
    int n = blockIdx.x;
    int tid = threadIdx.x;
    int off = g_segoff[n];
    int cnt = n_words[n];
    float inv = 1.f / (float)cnt;
    for (int c = tid; c < 512; c += 256) {
        float a = 0.f;
        for (int w = 0; w < cnt; w++) {
            int wc = word_code[off + w];
            a += g_xflat[wc * 512 + c];
        }
        out[n * 512 + c] = a * inv;
    }
}

extern "C" void kernel_launch(void* const* d_in, const int* in_sizes, int n_in,
                              void* d_out, int out_size) {
    const float* char_emb = (const float*)d_in[0];
    const float* Wc       = (const float*)d_in[1];
    const float* bc       = (const float*)d_in[2];
    const float* Wp       = (const float*)d_in[3];
    const float* bp       = (const float*)d_in[4];
    const float* gamma    = (const float*)d_in[5];
    const float* beta     = (const float*)d_in[6];
    const float* W1       = (const float*)d_in[7];
    const float* b1       = (const float*)d_in[8];
    const float* W2       = (const float*)d_in[9];
    const float* b2       = (const float*)d_in[10];
    const int* char_code  = (const int*)d_in[11];
    const int* word_code  = (const int*)d_in[12];
    const int* n_words    = (const int*)d_in[13];
    float* out = (float*)d_out;

    prep_kernel<<<272, 256>>>(Wp, bp, char_emb, Wc, bc);     // 1
    charqk_mma_kernel<<<dim3(16, 16, 8), 256>>>();           // 2
    transcp_kernel<<<18434, 256>>>(n_words);                 // 3
    attn_kernel<<<B_SZ, 256>>>(char_code, gamma, beta);      // 4 <- profiled
    mlp_kernel<<<B_SZ / 2, 128>>>(W1, b1, W2, b2);           // 5
    seg_kernel<<<N_NAMES, 256>>>(word_code, n_words, out);   // 6
}